// round 4
// baseline (speedup 1.0000x reference)
#include <cuda_runtime.h>
#include <cuda_bf16.h>
#include <cstdint>

#define BB 32
#define TT 64
#define SS 128
#define EE 256
#define HH 512
#define ENCC 512
#define VV 32000

// ---------------- scratch (device globals; no allocation) ----------------
__device__ float g_gatesx[BB * TT * 4 * HH];        // 16 MB  [b,t,4H]
__device__ float g_proj_enc[BB * SS * HH];          // 8 MB   [b,s,h]  enc @ Wa^T
__device__ float g_proj2[BB * SS * HH];             // 8 MB   [b,s,h]  enc @ Wc_c^T
__device__ float g_hbuf[2 * BB * HH];               // double-buffered h
__device__ float g_c[BB * HH];
__device__ float g_att[BB * SS];
__device__ float g_ho[BB * TT * HH];                // 4 MB
__device__ float g_bias2[4 * HH];                   // b_ih + b_hh

// ---------------- helpers ----------------
__device__ __forceinline__ uint32_t f2tf32(float x) {
    uint32_t r;
    asm("cvt.rna.tf32.f32 %0, %1;" : "=r"(r) : "f"(x));
    return r;
}

__device__ __forceinline__ void mma_tf32(float* d, const uint32_t* a, const uint32_t* b) {
    asm("mma.sync.aligned.m16n8k8.row.col.f32.tf32.tf32.f32 "
        "{%0,%1,%2,%3}, {%4,%5,%6,%7}, {%8,%9}, {%0,%1,%2,%3};"
        : "+f"(d[0]), "+f"(d[1]), "+f"(d[2]), "+f"(d[3])
        : "r"(a[0]), "r"(a[1]), "r"(a[2]), "r"(a[3]), "r"(b[0]), "r"(b[1]));
}

__device__ __forceinline__ float sigf(float x) { return 1.0f / (1.0f + expf(-x)); }

// ---------------- generic tf32 GEMM: C[M,N] = A[M,K] @ B[N,K]^T (+bias) -------------
// grid: (N/128, M/128), 256 threads. M,N multiples of 128; K multiple of KT.
// COMP: 3-term hi/lo compensation (~fp32 accuracy). GATHER: A row via gidx.
template <bool COMP, bool GATHER>
__global__ __launch_bounds__(256) void gemm_tf32(
    const float* __restrict__ A, int lda, const int* __restrict__ gidx,
    const float* __restrict__ B, int ldb,
    float* __restrict__ C, int ldc,
    const float* __restrict__ bias0, int K)
{
    constexpr int KT = COMP ? 16 : 32;
    constexpr int PAD = COMP ? 20 : 36;     // floats per smem row (conflict-free)
    constexpr int PLANE = 128 * PAD;
    constexpr int C4 = KT / 4;              // float4 per row
    constexpr int NL = (128 * C4) / 256;    // float4 loads per thread

    __shared__ uint32_t As[(COMP ? 2 : 1) * PLANE];
    __shared__ uint32_t Bs[(COMP ? 2 : 1) * PLANE];

    const int tid = threadIdx.x;
    const int warp = tid >> 5, lane = tid & 31;
    const int g = lane >> 2, tg = lane & 3;
    const int wm = (warp & 1) * 64, wn = (warp >> 1) * 32;
    const long m0 = (long)blockIdx.y * 128, n0 = (long)blockIdx.x * 128;

    float acc[4][4][4];
#pragma unroll
    for (int i = 0; i < 4; i++)
#pragma unroll
        for (int j = 0; j < 4; j++)
#pragma unroll
            for (int q = 0; q < 4; q++) acc[i][j][q] = 0.0f;

    for (int kt = 0; kt < K; kt += KT) {
#pragma unroll
        for (int i = 0; i < NL; i++) {
            int idx = i * 256 + tid;
            int row = idx / C4, c4 = idx % C4;
            const float* ap = GATHER ? (A + (size_t)gidx[m0 + row] * lda)
                                     : (A + (size_t)(m0 + row) * lda);
            float4 va = *(const float4*)(ap + kt + c4 * 4);
            const float* bp = B + (size_t)(n0 + row) * ldb;
            float4 vb = *(const float4*)(bp + kt + c4 * 4);
            uint32_t* da = &As[row * PAD + c4 * 4];
            uint32_t* db = &Bs[row * PAD + c4 * 4];
            float av[4] = {va.x, va.y, va.z, va.w};
            float bv[4] = {vb.x, vb.y, vb.z, vb.w};
#pragma unroll
            for (int q = 0; q < 4; q++) {
                uint32_t ah = f2tf32(av[q]);
                uint32_t bh = f2tf32(bv[q]);
                da[q] = ah;
                db[q] = bh;
                if (COMP) {
                    da[q + PLANE] = f2tf32(av[q] - __uint_as_float(ah));
                    db[q + PLANE] = f2tf32(bv[q] - __uint_as_float(bh));
                }
            }
        }
        __syncthreads();

#pragma unroll
        for (int ks = 0; ks < KT / 8; ks++) {
            const int k0 = ks * 8;
            uint32_t ah[4][4], bh[4][2];
#pragma unroll
            for (int mt = 0; mt < 4; mt++) {
                int rb = wm + mt * 16;
                ah[mt][0] = As[(rb + g) * PAD + k0 + tg];
                ah[mt][1] = As[(rb + g + 8) * PAD + k0 + tg];
                ah[mt][2] = As[(rb + g) * PAD + k0 + tg + 4];
                ah[mt][3] = As[(rb + g + 8) * PAD + k0 + tg + 4];
            }
#pragma unroll
            for (int nt = 0; nt < 4; nt++) {
                int nb = wn + nt * 8 + g;
                bh[nt][0] = Bs[nb * PAD + k0 + tg];
                bh[nt][1] = Bs[nb * PAD + k0 + tg + 4];
            }
            if (COMP) {
                uint32_t al[4][4], bl[4][2];
#pragma unroll
                for (int mt = 0; mt < 4; mt++) {
                    int rb = wm + mt * 16;
                    al[mt][0] = As[PLANE + (rb + g) * PAD + k0 + tg];
                    al[mt][1] = As[PLANE + (rb + g + 8) * PAD + k0 + tg];
                    al[mt][2] = As[PLANE + (rb + g) * PAD + k0 + tg + 4];
                    al[mt][3] = As[PLANE + (rb + g + 8) * PAD + k0 + tg + 4];
                }
#pragma unroll
                for (int nt = 0; nt < 4; nt++) {
                    int nb = wn + nt * 8 + g;
                    bl[nt][0] = Bs[PLANE + nb * PAD + k0 + tg];
                    bl[nt][1] = Bs[PLANE + nb * PAD + k0 + tg + 4];
                }
#pragma unroll
                for (int mt = 0; mt < 4; mt++)
#pragma unroll
                    for (int nt = 0; nt < 4; nt++) {
                        mma_tf32(acc[mt][nt], ah[mt], bh[nt]);
                        mma_tf32(acc[mt][nt], al[mt], bh[nt]);
                        mma_tf32(acc[mt][nt], ah[mt], bl[nt]);
                    }
            } else {
#pragma unroll
                for (int mt = 0; mt < 4; mt++)
#pragma unroll
                    for (int nt = 0; nt < 4; nt++)
                        mma_tf32(acc[mt][nt], ah[mt], bh[nt]);
            }
        }
        __syncthreads();
    }

    // epilogue
#pragma unroll
    for (int nt = 0; nt < 4; nt++) {
        long col = n0 + wn + nt * 8 + 2 * tg;
        float bv0 = bias0 ? bias0[col] : 0.0f;
        float bv1 = bias0 ? bias0[col + 1] : 0.0f;
#pragma unroll
        for (int mt = 0; mt < 4; mt++) {
            long row = m0 + wm + mt * 16 + g;
            float2 r0 = make_float2(acc[mt][nt][0] + bv0, acc[mt][nt][1] + bv1);
            float2 r1 = make_float2(acc[mt][nt][2] + bv0, acc[mt][nt][3] + bv1);
            *(float2*)(C + row * ldc + col) = r0;
            *(float2*)(C + (row + 8) * ldc + col) = r1;
        }
    }
}

// ---------------- bias combine ----------------
__global__ void k_bias(const float* __restrict__ a, const float* __restrict__ b) {
    int i = blockIdx.x * 256 + threadIdx.x;
    if (i < 4 * HH) g_bias2[i] = a[i] + b[i];
}

// ---------------- per-step: (optional) ho(t-1), then gates+LSTM(t) ----------------
// grid (4, 32): x = h-chunk (128 each), y = batch. 256 threads.
__global__ __launch_bounds__(256) void k_gatestep(
    const float* __restrict__ Whh, const float* __restrict__ Wcw,
    const float* __restrict__ Wcb, int t, int doHo, int doGates)
{
    __shared__ __align__(16) float h_sh[HH];
    __shared__ float att_sh[SS];
    __shared__ float gbuf[4 * 128];
    __shared__ float hopart[256];

    const int b = blockIdx.y, chunk = blockIdx.x, tid = threadIdx.x;
    const float* hprev = g_hbuf + (size_t)(t & 1) * (BB * HH) + (size_t)b * HH;

    h_sh[tid] = hprev[tid];
    h_sh[tid + 256] = hprev[tid + 256];
    if (doHo && tid < SS) att_sh[tid] = g_att[b * SS + tid];
    __syncthreads();

    if (doHo) {
        const int j = tid & 127, half = tid >> 7;
        const int jg = chunk * 128 + j;
        float acc = 0.0f;
        const float4* w4 = (const float4*)(Wcw + (size_t)jg * (HH + ENCC) + half * 256);
        const float4* h4 = (const float4*)(h_sh + half * 256);
#pragma unroll 4
        for (int k = 0; k < 64; k++) {
            float4 w = w4[k], h = h4[k];
            acc += w.x * h.x + w.y * h.y + w.z * h.z + w.w * h.w;
        }
        const float* p2 = g_proj2 + ((size_t)b * SS) * HH + jg;
        for (int s = half * 64; s < half * 64 + 64; s++)
            acc += att_sh[s] * p2[(size_t)s * HH];
        hopart[tid] = acc;
        __syncthreads();
        if (tid < 128) {
            g_ho[((size_t)b * TT + (t - 1)) * HH + chunk * 128 + tid] =
                hopart[tid] + hopart[tid + 128] + Wcb[chunk * 128 + tid];
        }
        __syncthreads();
    }

    if (doGates) {
        float* hnext = g_hbuf + (size_t)((t + 1) & 1) * (BB * HH) + (size_t)b * HH;
#pragma unroll
        for (int rep = 0; rep < 2; rep++) {
            int u = tid + rep * 256;                 // local 0..511 = z*128+j
            int z = u >> 7, j = u & 127;
            int r = z * HH + chunk * 128 + j;        // row in [4H]
            float acc = g_gatesx[((size_t)b * TT + t) * (4 * HH) + r];
            const float4* w4 = (const float4*)(Whh + (size_t)r * HH);
            const float4* h4 = (const float4*)h_sh;
#pragma unroll 4
            for (int k = 0; k < HH / 4; k++) {
                float4 w = w4[k], h = h4[k];
                acc += w.x * h.x + w.y * h.y + w.z * h.z + w.w * h.w;
            }
            gbuf[u] = acc;
        }
        __syncthreads();
        if (tid < 128) {
            int jg = chunk * 128 + tid;
            float iv = gbuf[tid];
            float fv = gbuf[128 + tid];
            float gv = gbuf[256 + tid];
            float ov = gbuf[384 + tid];
            float c_old = g_c[b * HH + jg];
            float cn = sigf(fv) * c_old + sigf(iv) * tanhf(gv);
            float hn = sigf(ov) * tanhf(cn);
            g_c[b * HH + jg] = cn;
            hnext[jg] = hn;
        }
    }
}

// ---------------- per-step attention: scores -> softmax -> att ----------------
// grid 32 (batch), 256 threads
__global__ __launch_bounds__(256) void k_att(int t, const int* __restrict__ lens) {
    __shared__ __align__(16) float h_sh[HH];
    __shared__ float red[256];
    __shared__ float sb[2];

    const int b = blockIdx.x, tid = threadIdx.x;
    const float* hc = g_hbuf + (size_t)((t + 1) & 1) * (BB * HH) + (size_t)b * HH;
    h_sh[tid] = hc[tid];
    h_sh[tid + 256] = hc[tid + 256];
    __syncthreads();

    const int s = tid & 127, half = tid >> 7;
    const float4* pr = (const float4*)(g_proj_enc + ((size_t)b * SS + s) * HH + half * 256);
    const float4* h4 = (const float4*)(h_sh + half * 256);
    float part = 0.0f;
#pragma unroll 4
    for (int k = 0; k < 64; k++) {
        float4 p = pr[k], h = h4[k];
        part += p.x * h.x + p.y * h.y + p.z * h.z + p.w * h.w;
    }
    red[tid] = part;
    __syncthreads();

    const int len = lens[b];
    float sc = 0.0f;
    bool valid = false;
    if (tid < 128) {
        sc = red[tid] + red[tid + 128];
        valid = tid < len;
    }
    __syncthreads();
    red[tid] = (tid < 128 && valid) ? sc : -3.0e38f;
    __syncthreads();
    for (int off = 128; off > 0; off >>= 1) {
        if (tid < off) red[tid] = fmaxf(red[tid], red[tid + off]);
        __syncthreads();
    }
    if (tid == 0) sb[0] = red[0];
    __syncthreads();
    float e = (tid < 128 && valid) ? expf(sc - sb[0]) : 0.0f;
    red[tid] = e;
    __syncthreads();
    for (int off = 128; off > 0; off >>= 1) {
        if (tid < off) red[tid] += red[tid + off];
        __syncthreads();
    }
    if (tid == 0) sb[1] = red[0];
    __syncthreads();
    if (tid < 128) g_att[b * SS + tid] = e / sb[1];
}

// ---------------- launcher ----------------
extern "C" void kernel_launch(void* const* d_in, const int* in_sizes, int n_in,
                              void* d_out, int out_size)
{
    const int* tok = (const int*)d_in[0];
    const float* enc = (const float*)d_in[1];
    const int* lens = (const int*)d_in[2];
    const float* h0 = (const float*)d_in[3];
    const float* c0 = (const float*)d_in[4];
    const float* emb = (const float*)d_in[5];
    const float* Wih = (const float*)d_in[6];
    const float* Whh = (const float*)d_in[7];
    const float* bih = (const float*)d_in[8];
    const float* bhh = (const float*)d_in[9];
    const float* Wa = (const float*)d_in[10];
    const float* Wcw = (const float*)d_in[11];
    const float* Wcb = (const float*)d_in[12];
    const float* Wow = (const float*)d_in[13];
    const float* Wob = (const float*)d_in[14];
    float* out = (float*)d_out;

    float *p_gatesx, *p_proj, *p_proj2, *p_hbuf, *p_c, *p_ho;
    cudaGetSymbolAddress((void**)&p_gatesx, g_gatesx);
    cudaGetSymbolAddress((void**)&p_proj, g_proj_enc);
    cudaGetSymbolAddress((void**)&p_proj2, g_proj2);
    cudaGetSymbolAddress((void**)&p_hbuf, g_hbuf);
    cudaGetSymbolAddress((void**)&p_c, g_c);
    cudaGetSymbolAddress((void**)&p_ho, g_ho);
    float* p_bias;
    cudaGetSymbolAddress((void**)&p_bias, g_bias2);

    // init recurrent state (h0 -> buffer 0, read at t=0)
    cudaMemcpyAsync(p_hbuf, h0, (size_t)BB * HH * sizeof(float),
                    cudaMemcpyDeviceToDevice, 0);
    cudaMemcpyAsync(p_c, c0, (size_t)BB * HH * sizeof(float),
                    cudaMemcpyDeviceToDevice, 0);

    k_bias<<<8, 256>>>(bih, bhh);

    // A1: gates_x[B*T, 4H] = emb[tok] @ W_ih^T + (b_ih+b_hh)   (tf32)
    gemm_tf32<false, true><<<dim3(4 * HH / 128, BB * TT / 128), 256>>>(
        emb, EE, tok, Wih, EE, p_gatesx, 4 * HH, p_bias, EE);

    // A2: proj_enc[B*S, H] = enc @ Wa^T   (compensated tf32 ~ fp32)
    gemm_tf32<true, false><<<dim3(HH / 128, BB * SS / 128), 256>>>(
        enc, ENCC, nullptr, Wa, ENCC, p_proj, HH, nullptr, ENCC);

    // A3: proj2[B*S, H] = enc @ Wc_c^T   (Wc_c = Wc_w[:, H:], row stride H+ENC)
    gemm_tf32<true, false><<<dim3(HH / 128, BB * SS / 128), 256>>>(
        enc, ENCC, nullptr, Wcw + HH, HH + ENCC, p_proj2, HH, nullptr, ENCC);

    // sequential decode
    for (int t = 0; t < TT; t++) {
        k_gatestep<<<dim3(4, BB), 256>>>(Whh, Wcw, Wcb, t, t > 0 ? 1 : 0, 1);
        k_att<<<BB, 256>>>(t, lens);
    }
    // final ho(T-1)
    k_gatestep<<<dim3(4, BB), 256>>>(Whh, Wcw, Wcb, TT, 1, 0);

    // D: logits[B*T, V] = HO @ Wo^T + Wo_b   (tf32)
    gemm_tf32<false, false><<<dim3(VV / 128, BB * TT / 128), 256>>>(
        p_ho, HH, nullptr, Wow, HH, out, VV, Wob, HH);
}

// round 7
// speedup vs baseline: 2.4453x; 2.4453x over previous
#include <cuda_runtime.h>
#include <cuda_bf16.h>
#include <cstdint>

#define BB 32
#define TT 64
#define SS 128
#define EE 256
#define HH 512
#define ENCC 512
#define VV 32000
#define NDEC 32   // blocks in persistent decode kernel (one wave, co-resident)

// ---------------- scratch (device globals; no allocation) ----------------
__device__ float g_gatesx[BB * TT * 4 * HH];        // 16 MB [b,t,4H] = emb@Wih^T + bias
__device__ float g_hhist[BB * TT * HH];             // 4 MB  h after step t: [b,t,h]
__device__ float g_proj_enc[BB * SS * HH];          // 8 MB  enc @ Wa^T
__device__ float g_proj2[BB * SS * HH];             // 8 MB  enc @ Wc_c^T
__device__ float g_att2[BB * TT * SS];              // 1 MB  att per (b,t)
__device__ float g_ho[BB * TT * HH];                // 4 MB
__device__ float g_bias2[4 * HH];                   // b_ih + b_hh
__device__ unsigned g_bar[TT];                      // decode grid barrier counters

// ---------------- helpers ----------------
__device__ __forceinline__ uint32_t f2tf32(float x) {
    uint32_t r;
    asm("cvt.rna.tf32.f32 %0, %1;" : "=r"(r) : "f"(x));
    return r;
}

__device__ __forceinline__ void mma_tf32(float* d, const uint32_t* a, const uint32_t* b) {
    asm("mma.sync.aligned.m16n8k8.row.col.f32.tf32.tf32.f32 "
        "{%0,%1,%2,%3}, {%4,%5,%6,%7}, {%8,%9}, {%0,%1,%2,%3};"
        : "+f"(d[0]), "+f"(d[1]), "+f"(d[2]), "+f"(d[3])
        : "r"(a[0]), "r"(a[1]), "r"(a[2]), "r"(a[3]), "r"(b[0]), "r"(b[1]));
}

__device__ __forceinline__ float sigf(float x) { return 1.0f / (1.0f + expf(-x)); }

// ---------------- generic tf32 GEMM: C[M,N] = A[M,K] @ B[N,K]^T (+bias) -------------
template <bool COMP, bool GATHER>
__global__ __launch_bounds__(256) void gemm_tf32(
    const float* __restrict__ A, int lda, const int* __restrict__ gidx,
    const float* __restrict__ B, int ldb,
    float* __restrict__ C, int ldc,
    const float* __restrict__ bias0, int K)
{
    constexpr int KT = COMP ? 16 : 32;
    constexpr int PAD = COMP ? 20 : 36;
    constexpr int PLANE = 128 * PAD;
    constexpr int C4 = KT / 4;
    constexpr int NL = (128 * C4) / 256;

    __shared__ uint32_t As[(COMP ? 2 : 1) * PLANE];
    __shared__ uint32_t Bs[(COMP ? 2 : 1) * PLANE];

    const int tid = threadIdx.x;
    const int warp = tid >> 5, lane = tid & 31;
    const int g = lane >> 2, tg = lane & 3;
    const int wm = (warp & 1) * 64, wn = (warp >> 1) * 32;
    const long m0 = (long)blockIdx.y * 128, n0 = (long)blockIdx.x * 128;

    float acc[4][4][4];
#pragma unroll
    for (int i = 0; i < 4; i++)
#pragma unroll
        for (int j = 0; j < 4; j++)
#pragma unroll
            for (int q = 0; q < 4; q++) acc[i][j][q] = 0.0f;

    for (int kt = 0; kt < K; kt += KT) {
#pragma unroll
        for (int i = 0; i < NL; i++) {
            int idx = i * 256 + tid;
            int row = idx / C4, c4 = idx % C4;
            const float* ap = GATHER ? (A + (size_t)gidx[m0 + row] * lda)
                                     : (A + (size_t)(m0 + row) * lda);
            float4 va = *(const float4*)(ap + kt + c4 * 4);
            const float* bp = B + (size_t)(n0 + row) * ldb;
            float4 vb = *(const float4*)(bp + kt + c4 * 4);
            uint32_t* da = &As[row * PAD + c4 * 4];
            uint32_t* db = &Bs[row * PAD + c4 * 4];
            float av[4] = {va.x, va.y, va.z, va.w};
            float bv[4] = {vb.x, vb.y, vb.z, vb.w};
#pragma unroll
            for (int q = 0; q < 4; q++) {
                uint32_t ah = f2tf32(av[q]);
                uint32_t bh = f2tf32(bv[q]);
                da[q] = ah;
                db[q] = bh;
                if (COMP) {
                    da[q + PLANE] = f2tf32(av[q] - __uint_as_float(ah));
                    db[q + PLANE] = f2tf32(bv[q] - __uint_as_float(bh));
                }
            }
        }
        __syncthreads();

#pragma unroll
        for (int ks = 0; ks < KT / 8; ks++) {
            const int k0 = ks * 8;
            uint32_t ah[4][4], bh[4][2];
#pragma unroll
            for (int mt = 0; mt < 4; mt++) {
                int rb = wm + mt * 16;
                ah[mt][0] = As[(rb + g) * PAD + k0 + tg];
                ah[mt][1] = As[(rb + g + 8) * PAD + k0 + tg];
                ah[mt][2] = As[(rb + g) * PAD + k0 + tg + 4];
                ah[mt][3] = As[(rb + g + 8) * PAD + k0 + tg + 4];
            }
#pragma unroll
            for (int nt = 0; nt < 4; nt++) {
                int nb = wn + nt * 8 + g;
                bh[nt][0] = Bs[nb * PAD + k0 + tg];
                bh[nt][1] = Bs[nb * PAD + k0 + tg + 4];
            }
            if (COMP) {
                uint32_t al[4][4], bl[4][2];
#pragma unroll
                for (int mt = 0; mt < 4; mt++) {
                    int rb = wm + mt * 16;
                    al[mt][0] = As[PLANE + (rb + g) * PAD + k0 + tg];
                    al[mt][1] = As[PLANE + (rb + g + 8) * PAD + k0 + tg];
                    al[mt][2] = As[PLANE + (rb + g) * PAD + k0 + tg + 4];
                    al[mt][3] = As[PLANE + (rb + g + 8) * PAD + k0 + tg + 4];
                }
#pragma unroll
                for (int nt = 0; nt < 4; nt++) {
                    int nb = wn + nt * 8 + g;
                    bl[nt][0] = Bs[PLANE + nb * PAD + k0 + tg];
                    bl[nt][1] = Bs[PLANE + nb * PAD + k0 + tg + 4];
                }
#pragma unroll
                for (int mt = 0; mt < 4; mt++)
#pragma unroll
                    for (int nt = 0; nt < 4; nt++) {
                        mma_tf32(acc[mt][nt], ah[mt], bh[nt]);
                        mma_tf32(acc[mt][nt], al[mt], bh[nt]);
                        mma_tf32(acc[mt][nt], ah[mt], bl[nt]);
                    }
            } else {
#pragma unroll
                for (int mt = 0; mt < 4; mt++)
#pragma unroll
                    for (int nt = 0; nt < 4; nt++)
                        mma_tf32(acc[mt][nt], ah[mt], bh[nt]);
            }
        }
        __syncthreads();
    }

#pragma unroll
    for (int nt = 0; nt < 4; nt++) {
        long col = n0 + wn + nt * 8 + 2 * tg;
        float bv0 = bias0 ? bias0[col] : 0.0f;
        float bv1 = bias0 ? bias0[col + 1] : 0.0f;
#pragma unroll
        for (int mt = 0; mt < 4; mt++) {
            long row = m0 + wm + mt * 16 + g;
            float2 r0 = make_float2(acc[mt][nt][0] + bv0, acc[mt][nt][1] + bv1);
            float2 r1 = make_float2(acc[mt][nt][2] + bv0, acc[mt][nt][3] + bv1);
            *(float2*)(C + row * ldc + col) = r0;
            *(float2*)(C + (row + 8) * ldc + col) = r1;
        }
    }
}

// ---------------- init kernels (graph-capturable) ----------------
__global__ void k_zero_bar() {
    if (threadIdx.x < TT) g_bar[threadIdx.x] = 0u;
}

__global__ void k_bias(const float* __restrict__ a, const float* __restrict__ b) {
    int i = blockIdx.x * 256 + threadIdx.x;
    if (i < 4 * HH) g_bias2[i] = a[i] + b[i];
}

// ---------------- persistent decode: 64 LSTM steps, 32 co-resident blocks --------
// Block blk owns h indices [16*blk, 16*blk+16). Per step:
//   C[32 b, 64 n] = h(t-1)[32,512] @ Whh'[64,512]^T (comp tf32), n = z*16+jj.
//   += gates_x; LSTM pointwise; write h slice; atomic grid barrier.
// NOTE: static+dynamic smem = 62,976 B > 48 KB default -> REQUIRES the
// cudaFuncSetAttribute(MaxDynamicSharedMemorySize) opt-in in kernel_launch.
__global__ __launch_bounds__(256) void k_decode(
    const float* __restrict__ h0, const float* __restrict__ c0,
    const float* __restrict__ Whh)
{
    extern __shared__ uint32_t dynsm[];
    uint32_t* Ah = dynsm;                 // 32*68  h hi
    uint32_t* Bh = Ah + 32 * 68;          // 64*68  Whh hi
    uint32_t* Bl = Bh + 64 * 68;          // 64*68  Whh lo
    __shared__ uint32_t Al[32 * 68];      // h lo
    __shared__ float dmp[32 * 68];        // gate dump [b][n]
    __shared__ float csh[512];            // c state [b*16+jj]

    const int blk = blockIdx.x, tid = threadIdx.x;
    const int warp = tid >> 5, lane = tid & 31, g = lane >> 2, tg = lane & 3;
    const int jb = blk * 16;

    for (int u = tid; u < 512; u += 256) {
        int b = u >> 4, jj = u & 15;
        csh[u] = c0[b * HH + jb + jj];
    }
    __syncthreads();

    for (int t = 0; t < TT; t++) {
        float acc[2][4];
#pragma unroll
        for (int mt = 0; mt < 2; mt++)
#pragma unroll
            for (int q = 0; q < 4; q++) acc[mt][q] = 0.0f;

        for (int kt = 0; kt < HH; kt += 64) {
#pragma unroll
            for (int i = 0; i < 2; i++) {
                int idx = i * 256 + tid;
                int row = idx >> 4, c4 = idx & 15;
                const float4* src = (t == 0)
                    ? ((const float4*)(h0 + (size_t)row * HH + kt) + c4)
                    : ((const float4*)(g_hhist + ((size_t)row * TT + (t - 1)) * HH + kt) + c4);
                float4 v = __ldcg(src);
                float av[4] = {v.x, v.y, v.z, v.w};
                uint32_t* da = &Ah[row * 68 + c4 * 4];
                uint32_t* dl = &Al[row * 68 + c4 * 4];
#pragma unroll
                for (int q = 0; q < 4; q++) {
                    uint32_t h = f2tf32(av[q]);
                    da[q] = h;
                    dl[q] = f2tf32(av[q] - __uint_as_float(h));
                }
            }
#pragma unroll
            for (int i = 0; i < 4; i++) {
                int idx = i * 256 + tid;
                int row = idx >> 4, c4 = idx & 15;
                int z = row >> 4, jj = row & 15;
                float4 v = *((const float4*)(Whh + (size_t)(z * HH + jb + jj) * HH + kt) + c4);
                float bv[4] = {v.x, v.y, v.z, v.w};
                uint32_t* db = &Bh[row * 68 + c4 * 4];
                uint32_t* dl = &Bl[row * 68 + c4 * 4];
#pragma unroll
                for (int q = 0; q < 4; q++) {
                    uint32_t h = f2tf32(bv[q]);
                    db[q] = h;
                    dl[q] = f2tf32(bv[q] - __uint_as_float(h));
                }
            }
            __syncthreads();

#pragma unroll
            for (int ks = 0; ks < 8; ks++) {
                const int k0 = ks * 8;
                uint32_t ah[2][4], al2[2][4], bh[2], bl2[2];
#pragma unroll
                for (int mt = 0; mt < 2; mt++) {
                    int rb = mt * 16;
                    ah[mt][0] = Ah[(rb + g) * 68 + k0 + tg];
                    ah[mt][1] = Ah[(rb + g + 8) * 68 + k0 + tg];
                    ah[mt][2] = Ah[(rb + g) * 68 + k0 + tg + 4];
                    ah[mt][3] = Ah[(rb + g + 8) * 68 + k0 + tg + 4];
                    al2[mt][0] = Al[(rb + g) * 68 + k0 + tg];
                    al2[mt][1] = Al[(rb + g + 8) * 68 + k0 + tg];
                    al2[mt][2] = Al[(rb + g) * 68 + k0 + tg + 4];
                    al2[mt][3] = Al[(rb + g + 8) * 68 + k0 + tg + 4];
                }
                int nb = warp * 8 + g;
                bh[0] = Bh[nb * 68 + k0 + tg];
                bh[1] = Bh[nb * 68 + k0 + tg + 4];
                bl2[0] = Bl[nb * 68 + k0 + tg];
                bl2[1] = Bl[nb * 68 + k0 + tg + 4];
#pragma unroll
                for (int mt = 0; mt < 2; mt++) {
                    mma_tf32(acc[mt], ah[mt], bh);
                    mma_tf32(acc[mt], al2[mt], bh);
                    mma_tf32(acc[mt], ah[mt], bl2);
                }
            }
            __syncthreads();
        }

#pragma unroll
        for (int mt = 0; mt < 2; mt++) {
            int row = mt * 16 + g, col = warp * 8 + 2 * tg;
            dmp[row * 68 + col] = acc[mt][0];
            dmp[row * 68 + col + 1] = acc[mt][1];
            dmp[(row + 8) * 68 + col] = acc[mt][2];
            dmp[(row + 8) * 68 + col + 1] = acc[mt][3];
        }
        __syncthreads();

        for (int u = tid; u < 512; u += 256) {
            int b = u >> 4, jj = u & 15;
            size_t gbase = ((size_t)b * TT + t) * (4 * HH) + jb + jj;
            float iv = dmp[b * 68 + jj]      + g_gatesx[gbase];
            float fv = dmp[b * 68 + 16 + jj] + g_gatesx[gbase + HH];
            float gv = dmp[b * 68 + 32 + jj] + g_gatesx[gbase + 2 * HH];
            float ov = dmp[b * 68 + 48 + jj] + g_gatesx[gbase + 3 * HH];
            float cn = sigf(fv) * csh[u] + sigf(iv) * tanhf(gv);
            float hn = sigf(ov) * tanhf(cn);
            csh[u] = cn;
            __stcg(&g_hhist[((size_t)b * TT + t) * HH + jb + jj], hn);
        }
        __threadfence();
        __syncthreads();
        if (tid == 0) {
            atomicAdd(&g_bar[t], 1u);
            while (atomicAdd(&g_bar[t], 0u) < NDEC) {}
        }
        __syncthreads();
    }
}

// ---------------- post-loop: scores + softmax (parallel over b) ----------
__global__ __launch_bounds__(256) void k_scores(const int* __restrict__ lens)
{
    extern __shared__ uint32_t dynsm[];
    uint32_t* Ah = dynsm;                 // 64*20
    uint32_t* Al = Ah + 64 * 20;
    uint32_t* Bh = Al + 64 * 20;          // 128*20
    uint32_t* Bl = Bh + 128 * 20;
    float* sc = (float*)dynsm;            // 64*132 overlay (phase-separated)

    const int b = blockIdx.x, tid = threadIdx.x;
    const int warp = tid >> 5, lane = tid & 31, g = lane >> 2, tg = lane & 3;
    const int wm = (warp & 1) * 32, wn = (warp >> 1) * 32;

    float acc[2][4][4];
#pragma unroll
    for (int i = 0; i < 2; i++)
#pragma unroll
        for (int j = 0; j < 4; j++)
#pragma unroll
            for (int q = 0; q < 4; q++) acc[i][j][q] = 0.0f;

    for (int kt = 0; kt < HH; kt += 16) {
        {
            int row = tid >> 2, c4 = tid & 3;
            float4 v = *((const float4*)(g_hhist + ((size_t)b * TT + row) * HH + kt) + c4);
            float av[4] = {v.x, v.y, v.z, v.w};
            uint32_t* da = &Ah[row * 20 + c4 * 4];
            uint32_t* dl = &Al[row * 20 + c4 * 4];
#pragma unroll
            for (int q = 0; q < 4; q++) {
                uint32_t h = f2tf32(av[q]);
                da[q] = h;
                dl[q] = f2tf32(av[q] - __uint_as_float(h));
            }
        }
#pragma unroll
        for (int i = 0; i < 2; i++) {
            int idx = i * 256 + tid;
            int row = idx >> 2, c4 = idx & 3;
            float4 v = *((const float4*)(g_proj_enc + ((size_t)b * SS + row) * HH + kt) + c4);
            float bv[4] = {v.x, v.y, v.z, v.w};
            uint32_t* db = &Bh[row * 20 + c4 * 4];
            uint32_t* dl = &Bl[row * 20 + c4 * 4];
#pragma unroll
            for (int q = 0; q < 4; q++) {
                uint32_t h = f2tf32(bv[q]);
                db[q] = h;
                dl[q] = f2tf32(bv[q] - __uint_as_float(h));
            }
        }
        __syncthreads();
#pragma unroll
        for (int ks = 0; ks < 2; ks++) {
            const int k0 = ks * 8;
            uint32_t ah[2][4], al2[2][4], bh[4][2], bl2[4][2];
#pragma unroll
            for (int mt = 0; mt < 2; mt++) {
                int rb = wm + mt * 16;
                ah[mt][0] = Ah[(rb + g) * 20 + k0 + tg];
                ah[mt][1] = Ah[(rb + g + 8) * 20 + k0 + tg];
                ah[mt][2] = Ah[(rb + g) * 20 + k0 + tg + 4];
                ah[mt][3] = Ah[(rb + g + 8) * 20 + k0 + tg + 4];
                al2[mt][0] = Al[(rb + g) * 20 + k0 + tg];
                al2[mt][1] = Al[(rb + g + 8) * 20 + k0 + tg];
                al2[mt][2] = Al[(rb + g) * 20 + k0 + tg + 4];
                al2[mt][3] = Al[(rb + g + 8) * 20 + k0 + tg + 4];
            }
#pragma unroll
            for (int nt = 0; nt < 4; nt++) {
                int nb = wn + nt * 8 + g;
                bh[nt][0] = Bh[nb * 20 + k0 + tg];
                bh[nt][1] = Bh[nb * 20 + k0 + tg + 4];
                bl2[nt][0] = Bl[nb * 20 + k0 + tg];
                bl2[nt][1] = Bl[nb * 20 + k0 + tg + 4];
            }
#pragma unroll
            for (int mt = 0; mt < 2; mt++)
#pragma unroll
                for (int nt = 0; nt < 4; nt++) {
                    mma_tf32(acc[mt][nt], ah[mt], bh[nt]);
                    mma_tf32(acc[mt][nt], al2[mt], bh[nt]);
                    mma_tf32(acc[mt][nt], ah[mt], bl2[nt]);
                }
        }
        __syncthreads();
    }

#pragma unroll
    for (int mt = 0; mt < 2; mt++)
#pragma unroll
        for (int nt = 0; nt < 4; nt++) {
            int row = wm + mt * 16 + g, col = wn + nt * 8 + 2 * tg;
            sc[row * 132 + col] = acc[mt][nt][0];
            sc[row * 132 + col + 1] = acc[mt][nt][1];
            sc[(row + 8) * 132 + col] = acc[mt][nt][2];
            sc[(row + 8) * 132 + col + 1] = acc[mt][nt][3];
        }
    __syncthreads();

    const int len = lens[b];
    for (int i = 0; i < 8; i++) {
        int t = warp * 8 + i;
        float v[4], mx = -3.0e38f;
#pragma unroll
        for (int q = 0; q < 4; q++) {
            int s = lane + q * 32;
            v[q] = (s < len) ? sc[t * 132 + s] : -3.0e38f;
            mx = fmaxf(mx, v[q]);
        }
        for (int off = 16; off > 0; off >>= 1)
            mx = fmaxf(mx, __shfl_xor_sync(0xFFFFFFFFu, mx, off));
        float e[4], sum = 0.0f;
#pragma unroll
        for (int q = 0; q < 4; q++) {
            int s = lane + q * 32;
            e[q] = (s < len) ? expf(v[q] - mx) : 0.0f;
            sum += e[q];
        }
        for (int off = 16; off > 0; off >>= 1)
            sum += __shfl_xor_sync(0xFFFFFFFFu, sum, off);
        float inv = 1.0f / sum;
#pragma unroll
        for (int q = 0; q < 4; q++)
            g_att2[((size_t)b * TT + t) * SS + lane + q * 32] = e[q] * inv;
    }
}

// ---------------- post-loop: HO += att @ proj2 (batched per b) ----------
__global__ __launch_bounds__(256) void k_ctx()
{
    __shared__ float att_sh[TT * SS];
    const int b = blockIdx.y, jt = blockIdx.x, tid = threadIdx.x;

    for (int i = tid; i < TT * SS / 4; i += 256)
        ((float4*)att_sh)[i] = ((const float4*)(g_att2 + (size_t)b * TT * SS))[i];
    __syncthreads();

    const int j = jt * 128 + (tid & 127);
    const int th = tid >> 7;
    float acc[32];
#pragma unroll
    for (int tt = 0; tt < 32; tt++) acc[tt] = 0.0f;

    const float* p2 = g_proj2 + (size_t)b * SS * HH + j;
    const float* ar = att_sh + (th * 32) * SS;
#pragma unroll 4
    for (int s = 0; s < SS; s++) {
        float v = p2[(size_t)s * HH];
#pragma unroll
        for (int tt = 0; tt < 32; tt++)
            acc[tt] += ar[tt * SS + s] * v;
    }
#pragma unroll
    for (int tt = 0; tt < 32; tt++) {
        size_t o = ((size_t)b * TT + th * 32 + tt) * HH + j;
        g_ho[o] += acc[tt];
    }
}

// ---------------- launcher ----------------
extern "C" void kernel_launch(void* const* d_in, const int* in_sizes, int n_in,
                              void* d_out, int out_size)
{
    const int* tok = (const int*)d_in[0];
    const float* enc = (const float*)d_in[1];
    const int* lens = (const int*)d_in[2];
    const float* h0 = (const float*)d_in[3];
    const float* c0 = (const float*)d_in[4];
    const float* emb = (const float*)d_in[5];
    const float* Wih = (const float*)d_in[6];
    const float* Whh = (const float*)d_in[7];
    const float* bih = (const float*)d_in[8];
    const float* bhh = (const float*)d_in[9];
    const float* Wa = (const float*)d_in[10];
    const float* Wcw = (const float*)d_in[11];
    const float* Wcb = (const float*)d_in[12];
    const float* Wow = (const float*)d_in[13];
    const float* Wob = (const float*)d_in[14];
    float* out = (float*)d_out;

    float *p_gatesx, *p_hhist, *p_proj, *p_proj2, *p_ho, *p_bias;
    cudaGetSymbolAddress((void**)&p_gatesx, g_gatesx);
    cudaGetSymbolAddress((void**)&p_hhist, g_hhist);
    cudaGetSymbolAddress((void**)&p_proj, g_proj_enc);
    cudaGetSymbolAddress((void**)&p_proj2, g_proj2);
    cudaGetSymbolAddress((void**)&p_ho, g_ho);
    cudaGetSymbolAddress((void**)&p_bias, g_bias2);

    // Opt in to >48KB combined shared memory for the persistent decode kernel.
    // (static 19,456 B + dynamic 43,520 B = 62,976 B — without this opt-in the
    //  launch fails with invalid argument, which is what broke graph capture.)
    const int DEC_DYN = (32 * 68 + 2 * 64 * 68) * 4;   // 43,520 B
    cudaFuncSetAttribute(k_decode, cudaFuncAttributeMaxDynamicSharedMemorySize, DEC_DYN);
    const int SC_DYN = 64 * 132 * 4;                    // 33,792 B (< 48KB, set anyway)
    cudaFuncSetAttribute(k_scores, cudaFuncAttributeMaxDynamicSharedMemorySize, SC_DYN);

    // reset decode grid-barrier counters via a KERNEL (capture-safe)
    k_zero_bar<<<1, 64>>>();
    k_bias<<<8, 256>>>(bih, bhh);

    // A1: gates_x[B*T, 4H] = emb[tok] @ W_ih^T + (b_ih + b_hh)
    gemm_tf32<false, true><<<dim3(4 * HH / 128, BB * TT / 128), 256>>>(
        emb, EE, tok, Wih, EE, p_gatesx, 4 * HH, p_bias, EE);

    // A2: proj_enc = enc @ Wa^T   (compensated tf32)
    gemm_tf32<true, false><<<dim3(HH / 128, BB * SS / 128), 256>>>(
        enc, ENCC, nullptr, Wa, ENCC, p_proj, HH, nullptr, ENCC);

    // A3: proj2 = enc @ Wc_c^T    (Wc_c = Wc_w[:, H:], row stride H+ENC)
    gemm_tf32<true, false><<<dim3(HH / 128, BB * SS / 128), 256>>>(
        enc, ENCC, nullptr, Wcw + HH, HH + ENCC, p_proj2, HH, nullptr, ENCC);

    // sequential LSTM recurrence: ONE persistent kernel, 64 steps internally
    k_decode<<<NDEC, 256, DEC_DYN>>>(h0, c0, Whh);

    // off-critical-path work, all parallel:
    k_scores<<<BB, 256, SC_DYN>>>(lens);

    // HO = Hhist @ Wc_h^T + Wcb   (compensated tf32; Wc_h = Wc_w[:, :H])
    gemm_tf32<true, false><<<dim3(HH / 128, BB * TT / 128), 256>>>(
        p_hhist, HH, nullptr, Wcw, HH + ENCC, p_ho, HH, Wcb, HH);

    k_ctx<<<dim3(4, BB), 256>>>();

    // D: logits = HO @ Wo^T + Wo_b
    gemm_tf32<false, false><<<dim3(VV / 128, BB * TT / 128), 256>>>(
        p_ho, HH, nullptr, Wow, HH, out, VV, Wob, HH);
}

// round 8
// speedup vs baseline: 2.6522x; 1.0846x over previous
#include <cuda_runtime.h>
#include <cuda_bf16.h>
#include <cstdint>

#define BB 32
#define TT 64
#define SS 128
#define EE 256
#define HH 512
#define ENCC 512
#define VV 32000
#define NDEC 32   // blocks in persistent decode kernel (one wave, co-resident)

// ---------------- scratch (device globals; no allocation) ----------------
__device__ float g_gatesx[BB * TT * 4 * HH];        // 16 MB [b,t,4H] = emb@Wih^T + bias
__device__ float g_hhist[BB * TT * HH];             // 4 MB  h after step t: [b,t,h]
__device__ float g_proj_enc[BB * SS * HH];          // 8 MB  enc @ Wa^T
__device__ float g_proj2[BB * SS * HH];             // 8 MB  enc @ Wc_c^T
__device__ float g_att2[BB * TT * SS];              // 1 MB  att per (b,t)
__device__ float g_ho[BB * TT * HH];                // 4 MB
__device__ float g_bias2[4 * HH];                   // b_ih + b_hh
__device__ unsigned g_bar[TT];                      // decode grid barrier counters

// ---------------- helpers ----------------
__device__ __forceinline__ uint32_t f2tf32(float x) {
    uint32_t r;
    asm("cvt.rna.tf32.f32 %0, %1;" : "=r"(r) : "f"(x));
    return r;
}

__device__ __forceinline__ void mma_tf32(float* d, const uint32_t* a, const uint32_t* b) {
    asm("mma.sync.aligned.m16n8k8.row.col.f32.tf32.tf32.f32 "
        "{%0,%1,%2,%3}, {%4,%5,%6,%7}, {%8,%9}, {%0,%1,%2,%3};"
        : "+f"(d[0]), "+f"(d[1]), "+f"(d[2]), "+f"(d[3])
        : "r"(a[0]), "r"(a[1]), "r"(a[2]), "r"(a[3]), "r"(b[0]), "r"(b[1]));
}

__device__ __forceinline__ float sigf(float x) { return 1.0f / (1.0f + expf(-x)); }

// ------- double-buffered tf32 GEMM: C[M,N] = A[M,K] @ B[N,K]^T (+bias) -----------
// grid: (N/128, M/128), 256 threads. Dynamic smem (2 stages x A/B tiles):
//   noncomp: 73,728 B ; comp: 81,920 B  -> requires MaxDynamicSharedMemorySize opt-in.
// Pipeline per KT tile: LDG(next)->regs | MMA(cur from smem) | cvt+STS(next) | sync.
template <bool COMP, bool GATHER>
__global__ __launch_bounds__(256) void gemm_db(
    const float* __restrict__ A, int lda, const int* __restrict__ gidx,
    const float* __restrict__ B, int ldb,
    float* __restrict__ C, int ldc,
    const float* __restrict__ bias0, int K)
{
    constexpr int KT = COMP ? 16 : 32;
    constexpr int PAD = COMP ? 20 : 36;     // floats per smem row (conflict-free)
    constexpr int PLANE = 128 * PAD;
    constexpr int NPL = COMP ? 2 : 1;       // planes per stage (hi[,lo])
    constexpr int STG = NPL * PLANE;        // uint32 per stage per array
    constexpr int C4 = KT / 4;              // float4 per row
    constexpr int NL = (128 * C4) / 256;    // float4 loads per thread per array

    extern __shared__ uint32_t sm[];
    uint32_t* As = sm;                      // 2 * STG
    uint32_t* Bs = sm + 2 * STG;            // 2 * STG

    const int tid = threadIdx.x;
    const int warp = tid >> 5, lane = tid & 31;
    const int g = lane >> 2, tg = lane & 3;
    const int wm = (warp & 1) * 64, wn = (warp >> 1) * 32;
    const long m0 = (long)blockIdx.y * 128, n0 = (long)blockIdx.x * 128;

    float acc[4][4][4];
#pragma unroll
    for (int i = 0; i < 4; i++)
#pragma unroll
        for (int j = 0; j < 4; j++)
#pragma unroll
            for (int q = 0; q < 4; q++) acc[i][j][q] = 0.0f;

    const int nk = K / KT;
    float4 ra[NL], rb[NL];

    auto ldg_tile = [&](int kt) {
#pragma unroll
        for (int i = 0; i < NL; i++) {
            int idx = i * 256 + tid;
            int row = idx / C4, c4 = idx % C4;
            const float* ap = GATHER ? (A + (size_t)gidx[m0 + row] * lda)
                                     : (A + (size_t)(m0 + row) * lda);
            ra[i] = *(const float4*)(ap + kt + c4 * 4);
            rb[i] = *(const float4*)(B + (size_t)(n0 + row) * ldb + kt + c4 * 4);
        }
    };
    auto sts_tile = [&](int stg) {
        uint32_t* as = As + stg * STG;
        uint32_t* bs = Bs + stg * STG;
#pragma unroll
        for (int i = 0; i < NL; i++) {
            int idx = i * 256 + tid;
            int row = idx / C4, c4 = idx % C4;
            uint32_t* da = &as[row * PAD + c4 * 4];
            uint32_t* db = &bs[row * PAD + c4 * 4];
            float av[4] = {ra[i].x, ra[i].y, ra[i].z, ra[i].w};
            float bv[4] = {rb[i].x, rb[i].y, rb[i].z, rb[i].w};
#pragma unroll
            for (int q = 0; q < 4; q++) {
                uint32_t ah = f2tf32(av[q]);
                uint32_t bh = f2tf32(bv[q]);
                da[q] = ah;
                db[q] = bh;
                if (COMP) {
                    da[q + PLANE] = f2tf32(av[q] - __uint_as_float(ah));
                    db[q + PLANE] = f2tf32(bv[q] - __uint_as_float(bh));
                }
            }
        }
    };

    // prologue: fill stage 0
    ldg_tile(0);
    sts_tile(0);
    __syncthreads();

    for (int ki = 0; ki < nk; ki++) {
        const int cur = ki & 1;
        if (ki + 1 < nk) ldg_tile((ki + 1) * KT);     // prefetch next tile into regs

        const uint32_t* Ac = As + cur * STG;
        const uint32_t* Bc = Bs + cur * STG;
#pragma unroll
        for (int ks = 0; ks < KT / 8; ks++) {
            const int k0 = ks * 8;
            uint32_t ah[4][4], bh[4][2];
#pragma unroll
            for (int mt = 0; mt < 4; mt++) {
                int rb2 = wm + mt * 16;
                ah[mt][0] = Ac[(rb2 + g) * PAD + k0 + tg];
                ah[mt][1] = Ac[(rb2 + g + 8) * PAD + k0 + tg];
                ah[mt][2] = Ac[(rb2 + g) * PAD + k0 + tg + 4];
                ah[mt][3] = Ac[(rb2 + g + 8) * PAD + k0 + tg + 4];
            }
#pragma unroll
            for (int nt = 0; nt < 4; nt++) {
                int nb = wn + nt * 8 + g;
                bh[nt][0] = Bc[nb * PAD + k0 + tg];
                bh[nt][1] = Bc[nb * PAD + k0 + tg + 4];
            }
            if (COMP) {
                uint32_t al[4][4], bl[4][2];
#pragma unroll
                for (int mt = 0; mt < 4; mt++) {
                    int rb2 = wm + mt * 16;
                    al[mt][0] = Ac[PLANE + (rb2 + g) * PAD + k0 + tg];
                    al[mt][1] = Ac[PLANE + (rb2 + g + 8) * PAD + k0 + tg];
                    al[mt][2] = Ac[PLANE + (rb2 + g) * PAD + k0 + tg + 4];
                    al[mt][3] = Ac[PLANE + (rb2 + g + 8) * PAD + k0 + tg + 4];
                }
#pragma unroll
                for (int nt = 0; nt < 4; nt++) {
                    int nb = wn + nt * 8 + g;
                    bl[nt][0] = Bc[PLANE + nb * PAD + k0 + tg];
                    bl[nt][1] = Bc[PLANE + nb * PAD + k0 + tg + 4];
                }
#pragma unroll
                for (int mt = 0; mt < 4; mt++)
#pragma unroll
                    for (int nt = 0; nt < 4; nt++) {
                        mma_tf32(acc[mt][nt], ah[mt], bh[nt]);
                        mma_tf32(acc[mt][nt], al[mt], bh[nt]);
                        mma_tf32(acc[mt][nt], ah[mt], bl[nt]);
                    }
            } else {
#pragma unroll
                for (int mt = 0; mt < 4; mt++)
#pragma unroll
                    for (int nt = 0; nt < 4; nt++)
                        mma_tf32(acc[mt][nt], ah[mt], bh[nt]);
            }
        }

        if (ki + 1 < nk) sts_tile(1 - cur);           // fill other stage
        __syncthreads();
    }

    // epilogue
#pragma unroll
    for (int nt = 0; nt < 4; nt++) {
        long col = n0 + wn + nt * 8 + 2 * tg;
        float bv0 = bias0 ? bias0[col] : 0.0f;
        float bv1 = bias0 ? bias0[col + 1] : 0.0f;
#pragma unroll
        for (int mt = 0; mt < 4; mt++) {
            long row = m0 + wm + mt * 16 + g;
            float2 r0 = make_float2(acc[mt][nt][0] + bv0, acc[mt][nt][1] + bv1);
            float2 r1 = make_float2(acc[mt][nt][2] + bv0, acc[mt][nt][3] + bv1);
            *(float2*)(C + row * ldc + col) = r0;
            *(float2*)(C + (row + 8) * ldc + col) = r1;
        }
    }
}

// ---------------- init kernels (graph-capturable) ----------------
__global__ void k_zero_bar() {
    if (threadIdx.x < TT) g_bar[threadIdx.x] = 0u;
}

__global__ void k_bias(const float* __restrict__ a, const float* __restrict__ b) {
    int i = blockIdx.x * 256 + threadIdx.x;
    if (i < 4 * HH) g_bias2[i] = a[i] + b[i];
}

// ---------------- persistent decode: 64 LSTM steps, 32 co-resident blocks --------
// Block blk owns h indices [16*blk, 16*blk+16). Per step:
//   C[32 b, 64 n] = h(t-1)[32,512] @ Whh'[64,512]^T (comp tf32), n = z*16+jj.
//   += gates_x; LSTM pointwise; write h slice; atomic grid barrier.
__global__ __launch_bounds__(256) void k_decode(
    const float* __restrict__ h0, const float* __restrict__ c0,
    const float* __restrict__ Whh)
{
    extern __shared__ uint32_t dynsm[];
    uint32_t* Ah = dynsm;                 // 32*68  h hi
    uint32_t* Bh = Ah + 32 * 68;          // 64*68  Whh hi
    uint32_t* Bl = Bh + 64 * 68;          // 64*68  Whh lo
    __shared__ uint32_t Al[32 * 68];      // h lo
    __shared__ float dmp[32 * 68];        // gate dump [b][n]
    __shared__ float csh[512];            // c state [b*16+jj]

    const int blk = blockIdx.x, tid = threadIdx.x;
    const int warp = tid >> 5, lane = tid & 31, g = lane >> 2, tg = lane & 3;
    const int jb = blk * 16;

    for (int u = tid; u < 512; u += 256) {
        int b = u >> 4, jj = u & 15;
        csh[u] = c0[b * HH + jb + jj];
    }
    __syncthreads();

    for (int t = 0; t < TT; t++) {
        float acc[2][4];
#pragma unroll
        for (int mt = 0; mt < 2; mt++)
#pragma unroll
            for (int q = 0; q < 4; q++) acc[mt][q] = 0.0f;

        for (int kt = 0; kt < HH; kt += 64) {
#pragma unroll
            for (int i = 0; i < 2; i++) {
                int idx = i * 256 + tid;
                int row = idx >> 4, c4 = idx & 15;
                const float4* src = (t == 0)
                    ? ((const float4*)(h0 + (size_t)row * HH + kt) + c4)
                    : ((const float4*)(g_hhist + ((size_t)row * TT + (t - 1)) * HH + kt) + c4);
                float4 v = __ldcg(src);
                float av[4] = {v.x, v.y, v.z, v.w};
                uint32_t* da = &Ah[row * 68 + c4 * 4];
                uint32_t* dl = &Al[row * 68 + c4 * 4];
#pragma unroll
                for (int q = 0; q < 4; q++) {
                    uint32_t h = f2tf32(av[q]);
                    da[q] = h;
                    dl[q] = f2tf32(av[q] - __uint_as_float(h));
                }
            }
#pragma unroll
            for (int i = 0; i < 4; i++) {
                int idx = i * 256 + tid;
                int row = idx >> 4, c4 = idx & 15;
                int z = row >> 4, jj = row & 15;
                float4 v = *((const float4*)(Whh + (size_t)(z * HH + jb + jj) * HH + kt) + c4);
                float bv[4] = {v.x, v.y, v.z, v.w};
                uint32_t* db = &Bh[row * 68 + c4 * 4];
                uint32_t* dl = &Bl[row * 68 + c4 * 4];
#pragma unroll
                for (int q = 0; q < 4; q++) {
                    uint32_t h = f2tf32(bv[q]);
                    db[q] = h;
                    dl[q] = f2tf32(bv[q] - __uint_as_float(h));
                }
            }
            __syncthreads();

#pragma unroll
            for (int ks = 0; ks < 8; ks++) {
                const int k0 = ks * 8;
                uint32_t ah[2][4], al2[2][4], bh[2], bl2[2];
#pragma unroll
                for (int mt = 0; mt < 2; mt++) {
                    int rb = mt * 16;
                    ah[mt][0] = Ah[(rb + g) * 68 + k0 + tg];
                    ah[mt][1] = Ah[(rb + g + 8) * 68 + k0 + tg];
                    ah[mt][2] = Ah[(rb + g) * 68 + k0 + tg + 4];
                    ah[mt][3] = Ah[(rb + g + 8) * 68 + k0 + tg + 4];
                    al2[mt][0] = Al[(rb + g) * 68 + k0 + tg];
                    al2[mt][1] = Al[(rb + g + 8) * 68 + k0 + tg];
                    al2[mt][2] = Al[(rb + g) * 68 + k0 + tg + 4];
                    al2[mt][3] = Al[(rb + g + 8) * 68 + k0 + tg + 4];
                }
                int nb = warp * 8 + g;
                bh[0] = Bh[nb * 68 + k0 + tg];
                bh[1] = Bh[nb * 68 + k0 + tg + 4];
                bl2[0] = Bl[nb * 68 + k0 + tg];
                bl2[1] = Bl[nb * 68 + k0 + tg + 4];
#pragma unroll
                for (int mt = 0; mt < 2; mt++) {
                    mma_tf32(acc[mt], ah[mt], bh);
                    mma_tf32(acc[mt], al2[mt], bh);
                    mma_tf32(acc[mt], ah[mt], bl2);
                }
            }
            __syncthreads();
        }

#pragma unroll
        for (int mt = 0; mt < 2; mt++) {
            int row = mt * 16 + g, col = warp * 8 + 2 * tg;
            dmp[row * 68 + col] = acc[mt][0];
            dmp[row * 68 + col + 1] = acc[mt][1];
            dmp[(row + 8) * 68 + col] = acc[mt][2];
            dmp[(row + 8) * 68 + col + 1] = acc[mt][3];
        }
        __syncthreads();

        for (int u = tid; u < 512; u += 256) {
            int b = u >> 4, jj = u & 15;
            size_t gbase = ((size_t)b * TT + t) * (4 * HH) + jb + jj;
            float iv = dmp[b * 68 + jj]      + g_gatesx[gbase];
            float fv = dmp[b * 68 + 16 + jj] + g_gatesx[gbase + HH];
            float gv = dmp[b * 68 + 32 + jj] + g_gatesx[gbase + 2 * HH];
            float ov = dmp[b * 68 + 48 + jj] + g_gatesx[gbase + 3 * HH];
            float cn = sigf(fv) * csh[u] + sigf(iv) * tanhf(gv);
            float hn = sigf(ov) * tanhf(cn);
            csh[u] = cn;
            __stcg(&g_hhist[((size_t)b * TT + t) * HH + jb + jj], hn);
        }
        __threadfence();
        __syncthreads();
        if (tid == 0) {
            atomicAdd(&g_bar[t], 1u);
            while (atomicAdd(&g_bar[t], 0u) < NDEC) {}
        }
        __syncthreads();
    }
}

// ---------------- post-loop: scores + softmax (parallel over b) ----------
__global__ __launch_bounds__(256) void k_scores(const int* __restrict__ lens)
{
    extern __shared__ uint32_t dynsm[];
    uint32_t* Ah = dynsm;                 // 64*20
    uint32_t* Al = Ah + 64 * 20;
    uint32_t* Bh = Al + 64 * 20;          // 128*20
    uint32_t* Bl = Bh + 128 * 20;
    float* sc = (float*)dynsm;            // 64*132 overlay (phase-separated)

    const int b = blockIdx.x, tid = threadIdx.x;
    const int warp = tid >> 5, lane = tid & 31, g = lane >> 2, tg = lane & 3;
    const int wm = (warp & 1) * 32, wn = (warp >> 1) * 32;

    float acc[2][4][4];
#pragma unroll
    for (int i = 0; i < 2; i++)
#pragma unroll
        for (int j = 0; j < 4; j++)
#pragma unroll
            for (int q = 0; q < 4; q++) acc[i][j][q] = 0.0f;

    for (int kt = 0; kt < HH; kt += 16) {
        {
            int row = tid >> 2, c4 = tid & 3;
            float4 v = *((const float4*)(g_hhist + ((size_t)b * TT + row) * HH + kt) + c4);
            float av[4] = {v.x, v.y, v.z, v.w};
            uint32_t* da = &Ah[row * 20 + c4 * 4];
            uint32_t* dl = &Al[row * 20 + c4 * 4];
#pragma unroll
            for (int q = 0; q < 4; q++) {
                uint32_t h = f2tf32(av[q]);
                da[q] = h;
                dl[q] = f2tf32(av[q] - __uint_as_float(h));
            }
        }
#pragma unroll
        for (int i = 0; i < 2; i++) {
            int idx = i * 256 + tid;
            int row = idx >> 2, c4 = idx & 3;
            float4 v = *((const float4*)(g_proj_enc + ((size_t)b * SS + row) * HH + kt) + c4);
            float bv[4] = {v.x, v.y, v.z, v.w};
            uint32_t* db = &Bh[row * 20 + c4 * 4];
            uint32_t* dl = &Bl[row * 20 + c4 * 4];
#pragma unroll
            for (int q = 0; q < 4; q++) {
                uint32_t h = f2tf32(bv[q]);
                db[q] = h;
                dl[q] = f2tf32(bv[q] - __uint_as_float(h));
            }
        }
        __syncthreads();
#pragma unroll
        for (int ks = 0; ks < 2; ks++) {
            const int k0 = ks * 8;
            uint32_t ah[2][4], al2[2][4], bh[4][2], bl2[4][2];
#pragma unroll
            for (int mt = 0; mt < 2; mt++) {
                int rb = wm + mt * 16;
                ah[mt][0] = Ah[(rb + g) * 20 + k0 + tg];
                ah[mt][1] = Ah[(rb + g + 8) * 20 + k0 + tg];
                ah[mt][2] = Ah[(rb + g) * 20 + k0 + tg + 4];
                ah[mt][3] = Ah[(rb + g + 8) * 20 + k0 + tg + 4];
                al2[mt][0] = Al[(rb + g) * 20 + k0 + tg];
                al2[mt][1] = Al[(rb + g + 8) * 20 + k0 + tg];
                al2[mt][2] = Al[(rb + g) * 20 + k0 + tg + 4];
                al2[mt][3] = Al[(rb + g + 8) * 20 + k0 + tg + 4];
            }
#pragma unroll
            for (int nt = 0; nt < 4; nt++) {
                int nb = wn + nt * 8 + g;
                bh[nt][0] = Bh[nb * 20 + k0 + tg];
                bh[nt][1] = Bh[nb * 20 + k0 + tg + 4];
                bl2[nt][0] = Bl[nb * 20 + k0 + tg];
                bl2[nt][1] = Bl[nb * 20 + k0 + tg + 4];
            }
#pragma unroll
            for (int mt = 0; mt < 2; mt++)
#pragma unroll
                for (int nt = 0; nt < 4; nt++) {
                    mma_tf32(acc[mt][nt], ah[mt], bh[nt]);
                    mma_tf32(acc[mt][nt], al2[mt], bh[nt]);
                    mma_tf32(acc[mt][nt], ah[mt], bl2[nt]);
                }
        }
        __syncthreads();
    }

#pragma unroll
    for (int mt = 0; mt < 2; mt++)
#pragma unroll
        for (int nt = 0; nt < 4; nt++) {
            int row = wm + mt * 16 + g, col = wn + nt * 8 + 2 * tg;
            sc[row * 132 + col] = acc[mt][nt][0];
            sc[row * 132 + col + 1] = acc[mt][nt][1];
            sc[(row + 8) * 132 + col] = acc[mt][nt][2];
            sc[(row + 8) * 132 + col + 1] = acc[mt][nt][3];
        }
    __syncthreads();

    const int len = lens[b];
    for (int i = 0; i < 8; i++) {
        int t = warp * 8 + i;
        float v[4], mx = -3.0e38f;
#pragma unroll
        for (int q = 0; q < 4; q++) {
            int s = lane + q * 32;
            v[q] = (s < len) ? sc[t * 132 + s] : -3.0e38f;
            mx = fmaxf(mx, v[q]);
        }
        for (int off = 16; off > 0; off >>= 1)
            mx = fmaxf(mx, __shfl_xor_sync(0xFFFFFFFFu, mx, off));
        float e[4], sum = 0.0f;
#pragma unroll
        for (int q = 0; q < 4; q++) {
            int s = lane + q * 32;
            e[q] = (s < len) ? expf(v[q] - mx) : 0.0f;
            sum += e[q];
        }
        for (int off = 16; off > 0; off >>= 1)
            sum += __shfl_xor_sync(0xFFFFFFFFu, sum, off);
        float inv = 1.0f / sum;
#pragma unroll
        for (int q = 0; q < 4; q++)
            g_att2[((size_t)b * TT + t) * SS + lane + q * 32] = e[q] * inv;
    }
}

// ---------------- post-loop: HO += att @ proj2 (batched per b) ----------
__global__ __launch_bounds__(256) void k_ctx()
{
    __shared__ float att_sh[TT * SS];
    const int b = blockIdx.y, jt = blockIdx.x, tid = threadIdx.x;

    for (int i = tid; i < TT * SS / 4; i += 256)
        ((float4*)att_sh)[i] = ((const float4*)(g_att2 + (size_t)b * TT * SS))[i];
    __syncthreads();

    const int j = jt * 128 + (tid & 127);
    const int th = tid >> 7;
    float acc[32];
#pragma unroll
    for (int tt = 0; tt < 32; tt++) acc[tt] = 0.0f;

    const float* p2 = g_proj2 + (size_t)b * SS * HH + j;
    const float* ar = att_sh + (th * 32) * SS;
#pragma unroll 4
    for (int s = 0; s < SS; s++) {
        float v = p2[(size_t)s * HH];
#pragma unroll
        for (int tt = 0; tt < 32; tt++)
            acc[tt] += ar[tt * SS + s] * v;
    }
#pragma unroll
    for (int tt = 0; tt < 32; tt++) {
        size_t o = ((size_t)b * TT + th * 32 + tt) * HH + j;
        g_ho[o] += acc[tt];
    }
}

// ---------------- launcher ----------------
extern "C" void kernel_launch(void* const* d_in, const int* in_sizes, int n_in,
                              void* d_out, int out_size)
{
    const int* tok = (const int*)d_in[0];
    const float* enc = (const float*)d_in[1];
    const int* lens = (const int*)d_in[2];
    const float* h0 = (const float*)d_in[3];
    const float* c0 = (const float*)d_in[4];
    const float* emb = (const float*)d_in[5];
    const float* Wih = (const float*)d_in[6];
    const float* Whh = (const float*)d_in[7];
    const float* bih = (const float*)d_in[8];
    const float* bhh = (const float*)d_in[9];
    const float* Wa = (const float*)d_in[10];
    const float* Wcw = (const float*)d_in[11];
    const float* Wcb = (const float*)d_in[12];
    const float* Wow = (const float*)d_in[13];
    const float* Wob = (const float*)d_in[14];
    float* out = (float*)d_out;

    float *p_gatesx, *p_hhist, *p_proj, *p_proj2, *p_ho, *p_bias;
    cudaGetSymbolAddress((void**)&p_gatesx, g_gatesx);
    cudaGetSymbolAddress((void**)&p_hhist, g_hhist);
    cudaGetSymbolAddress((void**)&p_proj, g_proj_enc);
    cudaGetSymbolAddress((void**)&p_proj2, g_proj2);
    cudaGetSymbolAddress((void**)&p_ho, g_ho);
    cudaGetSymbolAddress((void**)&p_bias, g_bias2);

    // smem opt-ins (one per template instantiation!)
    const int NC_DYN = 2 * 2 * (128 * 36) * 4;          // 73,728 B  (noncomp, 2-stage A+B)
    const int CP_DYN = 2 * 2 * (2 * 128 * 20) * 4;      // 81,920 B  (comp, hi+lo planes)
    cudaFuncSetAttribute(gemm_db<false, true>,  cudaFuncAttributeMaxDynamicSharedMemorySize, NC_DYN);
    cudaFuncSetAttribute(gemm_db<false, false>, cudaFuncAttributeMaxDynamicSharedMemorySize, NC_DYN);
    cudaFuncSetAttribute(gemm_db<true, false>,  cudaFuncAttributeMaxDynamicSharedMemorySize, CP_DYN);

    const int DEC_DYN = (32 * 68 + 2 * 64 * 68) * 4;    // 43,520 B
    cudaFuncSetAttribute(k_decode, cudaFuncAttributeMaxDynamicSharedMemorySize, DEC_DYN);
    const int SC_DYN = 64 * 132 * 4;                    // 33,792 B
    cudaFuncSetAttribute(k_scores, cudaFuncAttributeMaxDynamicSharedMemorySize, SC_DYN);

    // reset decode grid-barrier counters via a KERNEL (capture-safe)
    k_zero_bar<<<1, 64>>>();
    k_bias<<<8, 256>>>(bih, bhh);

    // A1: gates_x[B*T, 4H] = emb[tok] @ W_ih^T + (b_ih + b_hh)
    gemm_db<false, true><<<dim3(4 * HH / 128, BB * TT / 128), 256, NC_DYN>>>(
        emb, EE, tok, Wih, EE, p_gatesx, 4 * HH, p_bias, EE);

    // A2: proj_enc = enc @ Wa^T   (compensated tf32)
    gemm_db<true, false><<<dim3(HH / 128, BB * SS / 128), 256, CP_DYN>>>(
        enc, ENCC, nullptr, Wa, ENCC, p_proj, HH, nullptr, ENCC);

    // A3: proj2 = enc @ Wc_c^T    (Wc_c = Wc_w[:, H:], row stride H+ENC)
    gemm_db<true, false><<<dim3(HH / 128, BB * SS / 128), 256, CP_DYN>>>(
        enc, ENCC, nullptr, Wcw + HH, HH + ENCC, p_proj2, HH, nullptr, ENCC);

    // sequential LSTM recurrence: ONE persistent kernel, 64 steps internally
    k_decode<<<NDEC, 256, DEC_DYN>>>(h0, c0, Whh);

    // off-critical-path work, all parallel:
    k_scores<<<BB, 256, SC_DYN>>>(lens);

    // HO = Hhist @ Wc_h^T + Wcb   (compensated tf32; Wc_h = Wc_w[:, :H])
    gemm_db<true, false><<<dim3(HH / 128, BB * TT / 128), 256, CP_DYN>>>(
        p_hhist, HH, nullptr, Wcw, HH + ENCC, p_ho, HH, Wcb, HH);

    k_ctx<<<dim3(4, BB), 256>>>();

    // D: logits = HO @ Wo^T + Wo_b
    gemm_db<false, false><<<dim3(VV / 128, BB * TT / 128), 256, NC_DYN>>>(
        p_ho, HH, nullptr, Wow, HH, out, VV, Wob, HH);
}

// round 9
// speedup vs baseline: 2.8114x; 1.0600x over previous
#include <cuda_runtime.h>
#include <cuda_bf16.h>
#include <cstdint>

#define BB 32
#define TT 64
#define SS 128
#define EE 256
#define HH 512
#define ENCC 512
#define VV 32000
#define NDEC 32   // blocks in persistent decode kernel (one wave, co-resident)

// ---------------- scratch (device globals; no allocation) ----------------
__device__ float g_gatesx[BB * TT * 4 * HH];        // 16 MB [b,t,4H] = emb@Wih^T + bias
__device__ float g_hhist[BB * TT * HH];             // 4 MB  h after step t: [b,t,h]
__device__ float g_proj_enc[BB * SS * HH];          // 8 MB  enc @ Wa^T
__device__ float g_proj2[BB * SS * HH];             // 8 MB  enc @ Wc_c^T
__device__ float g_att2[BB * TT * SS];              // 1 MB  att per (b,t)
__device__ float g_ho[BB * TT * HH];                // 4 MB
__device__ float g_bias2[4 * HH];                   // b_ih + b_hh
__device__ unsigned g_bar[TT];                      // decode grid barrier counters
// tf32 hi/lo planes (precomputed once per launch):
__device__ uint32_t g_whh_hi[4 * HH * HH];          // 4 MB, rearranged [blk][z][jj][k]
__device__ uint32_t g_whh_lo[4 * HH * HH];          // 4 MB
__device__ uint32_t g_hpl[2][2][BB * HH];           // [parity][hi/lo][b*H+j]

// ---------------- helpers ----------------
__device__ __forceinline__ uint32_t f2tf32(float x) {
    uint32_t r;
    asm("cvt.rna.tf32.f32 %0, %1;" : "=r"(r) : "f"(x));
    return r;
}

__device__ __forceinline__ void mma_tf32(float* d, const uint32_t* a, const uint32_t* b) {
    asm("mma.sync.aligned.m16n8k8.row.col.f32.tf32.tf32.f32 "
        "{%0,%1,%2,%3}, {%4,%5,%6,%7}, {%8,%9}, {%0,%1,%2,%3};"
        : "+f"(d[0]), "+f"(d[1]), "+f"(d[2]), "+f"(d[3])
        : "r"(a[0]), "r"(a[1]), "r"(a[2]), "r"(a[3]), "r"(b[0]), "r"(b[1]));
}

__device__ __forceinline__ float sigf(float x) { return 1.0f / (1.0f + expf(-x)); }

// ------- double-buffered tf32 GEMM: C[M,N] = A[M,K] @ B[N,K]^T (+bias) -----------
template <bool COMP, bool GATHER>
__global__ __launch_bounds__(256) void gemm_db(
    const float* __restrict__ A, int lda, const int* __restrict__ gidx,
    const float* __restrict__ B, int ldb,
    float* __restrict__ C, int ldc,
    const float* __restrict__ bias0, int K)
{
    constexpr int KT = COMP ? 16 : 32;
    constexpr int PAD = COMP ? 20 : 36;
    constexpr int PLANE = 128 * PAD;
    constexpr int NPL = COMP ? 2 : 1;
    constexpr int STG = NPL * PLANE;
    constexpr int C4 = KT / 4;
    constexpr int NL = (128 * C4) / 256;

    extern __shared__ uint32_t sm[];
    uint32_t* As = sm;
    uint32_t* Bs = sm + 2 * STG;

    const int tid = threadIdx.x;
    const int warp = tid >> 5, lane = tid & 31;
    const int g = lane >> 2, tg = lane & 3;
    const int wm = (warp & 1) * 64, wn = (warp >> 1) * 32;
    const long m0 = (long)blockIdx.y * 128, n0 = (long)blockIdx.x * 128;

    float acc[4][4][4];
#pragma unroll
    for (int i = 0; i < 4; i++)
#pragma unroll
        for (int j = 0; j < 4; j++)
#pragma unroll
            for (int q = 0; q < 4; q++) acc[i][j][q] = 0.0f;

    const int nk = K / KT;
    float4 ra[NL], rb[NL];

    auto ldg_tile = [&](int kt) {
#pragma unroll
        for (int i = 0; i < NL; i++) {
            int idx = i * 256 + tid;
            int row = idx / C4, c4 = idx % C4;
            const float* ap = GATHER ? (A + (size_t)gidx[m0 + row] * lda)
                                     : (A + (size_t)(m0 + row) * lda);
            ra[i] = *(const float4*)(ap + kt + c4 * 4);
            rb[i] = *(const float4*)(B + (size_t)(n0 + row) * ldb + kt + c4 * 4);
        }
    };
    auto sts_tile = [&](int stg) {
        uint32_t* as = As + stg * STG;
        uint32_t* bs = Bs + stg * STG;
#pragma unroll
        for (int i = 0; i < NL; i++) {
            int idx = i * 256 + tid;
            int row = idx / C4, c4 = idx % C4;
            uint32_t* da = &as[row * PAD + c4 * 4];
            uint32_t* db = &bs[row * PAD + c4 * 4];
            float av[4] = {ra[i].x, ra[i].y, ra[i].z, ra[i].w};
            float bv[4] = {rb[i].x, rb[i].y, rb[i].z, rb[i].w};
#pragma unroll
            for (int q = 0; q < 4; q++) {
                uint32_t ah = f2tf32(av[q]);
                uint32_t bh = f2tf32(bv[q]);
                da[q] = ah;
                db[q] = bh;
                if (COMP) {
                    da[q + PLANE] = f2tf32(av[q] - __uint_as_float(ah));
                    db[q + PLANE] = f2tf32(bv[q] - __uint_as_float(bh));
                }
            }
        }
    };

    ldg_tile(0);
    sts_tile(0);
    __syncthreads();

    for (int ki = 0; ki < nk; ki++) {
        const int cur = ki & 1;
        if (ki + 1 < nk) ldg_tile((ki + 1) * KT);

        const uint32_t* Ac = As + cur * STG;
        const uint32_t* Bc = Bs + cur * STG;
#pragma unroll
        for (int ks = 0; ks < KT / 8; ks++) {
            const int k0 = ks * 8;
            uint32_t ah[4][4], bh[4][2];
#pragma unroll
            for (int mt = 0; mt < 4; mt++) {
                int rb2 = wm + mt * 16;
                ah[mt][0] = Ac[(rb2 + g) * PAD + k0 + tg];
                ah[mt][1] = Ac[(rb2 + g + 8) * PAD + k0 + tg];
                ah[mt][2] = Ac[(rb2 + g) * PAD + k0 + tg + 4];
                ah[mt][3] = Ac[(rb2 + g + 8) * PAD + k0 + tg + 4];
            }
#pragma unroll
            for (int nt = 0; nt < 4; nt++) {
                int nb = wn + nt * 8 + g;
                bh[nt][0] = Bc[nb * PAD + k0 + tg];
                bh[nt][1] = Bc[nb * PAD + k0 + tg + 4];
            }
            if (COMP) {
                uint32_t al[4][4], bl[4][2];
#pragma unroll
                for (int mt = 0; mt < 4; mt++) {
                    int rb2 = wm + mt * 16;
                    al[mt][0] = Ac[PLANE + (rb2 + g) * PAD + k0 + tg];
                    al[mt][1] = Ac[PLANE + (rb2 + g + 8) * PAD + k0 + tg];
                    al[mt][2] = Ac[PLANE + (rb2 + g) * PAD + k0 + tg + 4];
                    al[mt][3] = Ac[PLANE + (rb2 + g + 8) * PAD + k0 + tg + 4];
                }
#pragma unroll
                for (int nt = 0; nt < 4; nt++) {
                    int nb = wn + nt * 8 + g;
                    bl[nt][0] = Bc[PLANE + nb * PAD + k0 + tg];
                    bl[nt][1] = Bc[PLANE + nb * PAD + k0 + tg + 4];
                }
#pragma unroll
                for (int mt = 0; mt < 4; mt++)
#pragma unroll
                    for (int nt = 0; nt < 4; nt++) {
                        mma_tf32(acc[mt][nt], ah[mt], bh[nt]);
                        mma_tf32(acc[mt][nt], al[mt], bh[nt]);
                        mma_tf32(acc[mt][nt], ah[mt], bl[nt]);
                    }
            } else {
#pragma unroll
                for (int mt = 0; mt < 4; mt++)
#pragma unroll
                    for (int nt = 0; nt < 4; nt++)
                        mma_tf32(acc[mt][nt], ah[mt], bh[nt]);
            }
        }

        if (ki + 1 < nk) sts_tile(1 - cur);
        __syncthreads();
    }

#pragma unroll
    for (int nt = 0; nt < 4; nt++) {
        long col = n0 + wn + nt * 8 + 2 * tg;
        float bv0 = bias0 ? bias0[col] : 0.0f;
        float bv1 = bias0 ? bias0[col + 1] : 0.0f;
#pragma unroll
        for (int mt = 0; mt < 4; mt++) {
            long row = m0 + wm + mt * 16 + g;
            float2 r0 = make_float2(acc[mt][nt][0] + bv0, acc[mt][nt][1] + bv1);
            float2 r1 = make_float2(acc[mt][nt][2] + bv0, acc[mt][nt][3] + bv1);
            *(float2*)(C + row * ldc + col) = r0;
            *(float2*)(C + (row + 8) * ldc + col) = r1;
        }
    }
}

// ---------------- init / prep kernels (graph-capturable) ----------------
__global__ void k_zero_bar() {
    if (threadIdx.x < TT) g_bar[threadIdx.x] = 0u;
}

__global__ void k_bias(const float* __restrict__ a, const float* __restrict__ b) {
    int i = blockIdx.x * 256 + threadIdx.x;
    if (i < 4 * HH) g_bias2[i] = a[i] + b[i];
}

// Split Whh into tf32 hi/lo planes, rearranged so decode block blk reads a
// contiguous 64x512 slice: out row o = blk*64 + z*16 + jj <- Whh row z*H + blk*16 + jj.
__global__ void k_prep_whh(const float* __restrict__ Whh) {
    int o4 = blockIdx.x * 256 + threadIdx.x;        // uint4 index over 2048*128
    if (o4 >= 2048 * 128) return;
    int o = o4 >> 7, c4 = o4 & 127;
    int blk = o >> 6, z = (o >> 4) & 3, jj = o & 15;
    float4 v = *((const float4*)(Whh + (size_t)(z * HH + blk * 16 + jj) * HH) + c4);
    float av[4] = {v.x, v.y, v.z, v.w};
    uint32_t hi[4], lo[4];
#pragma unroll
    for (int q = 0; q < 4; q++) {
        hi[q] = f2tf32(av[q]);
        lo[q] = f2tf32(av[q] - __uint_as_float(hi[q]));
    }
    *(uint4*)&g_whh_hi[(size_t)o * HH + c4 * 4] = *(uint4*)hi;
    *(uint4*)&g_whh_lo[(size_t)o * HH + c4 * 4] = *(uint4*)lo;
}

// h0 -> tf32 hi/lo planes, parity 0 (read at t=0).
__global__ void k_prep_h0(const float* __restrict__ h0) {
    int i4 = blockIdx.x * 256 + threadIdx.x;        // over 32*512/4
    if (i4 >= BB * HH / 4) return;
    float4 v = ((const float4*)h0)[i4];
    float av[4] = {v.x, v.y, v.z, v.w};
    uint32_t hi[4], lo[4];
#pragma unroll
    for (int q = 0; q < 4; q++) {
        hi[q] = f2tf32(av[q]);
        lo[q] = f2tf32(av[q] - __uint_as_float(hi[q]));
    }
    *(uint4*)&g_hpl[0][0][i4 * 4] = *(uint4*)hi;
    *(uint4*)&g_hpl[0][1][i4 * 4] = *(uint4*)lo;
}

// ---------------- persistent decode v2: precomputed tf32 planes, 2-stage pipe ----
// smem: 2 stages x [Ah 32x68 | Al 32x68 | Bh 64x68 | Bl 64x68] + dmp + csh = 115,200 B
__global__ __launch_bounds__(256) void k_decode(const float* __restrict__ c0)
{
    extern __shared__ uint32_t sm[];
    constexpr int ASZ = 32 * 68, BSZ = 64 * 68;
    constexpr int STG = 2 * ASZ + 2 * BSZ;          // 13056 words
    float* dmp = (float*)(sm + 2 * STG);            // 32*68 floats
    float* csh = dmp + 32 * 68;                     // 512 floats

    const int blk = blockIdx.x, tid = threadIdx.x;
    const int warp = tid >> 5, lane = tid & 31, g = lane >> 2, tg = lane & 3;
    const int jb = blk * 16;

    for (int u = tid; u < 512; u += 256)
        csh[u] = c0[(u >> 4) * HH + jb + (u & 15)];

    const uint32_t* whh_hi = g_whh_hi + (size_t)blk * 64 * HH;
    const uint32_t* whh_lo = g_whh_lo + (size_t)blk * 64 * HH;
    __syncthreads();

    for (int t = 0; t < TT; t++) {
        const uint32_t* hh = g_hpl[t & 1][0];
        const uint32_t* hl = g_hpl[t & 1][1];

        // prefetch this step's gates_x scalars (independent of h)
        float gx[2][4];
#pragma unroll
        for (int rep = 0; rep < 2; rep++) {
            int u = tid + rep * 256;
            size_t gbase = ((size_t)(u >> 4) * TT + t) * (4 * HH) + jb + (u & 15);
            gx[rep][0] = __ldcg(&g_gatesx[gbase]);
            gx[rep][1] = __ldcg(&g_gatesx[gbase + HH]);
            gx[rep][2] = __ldcg(&g_gatesx[gbase + 2 * HH]);
            gx[rep][3] = __ldcg(&g_gatesx[gbase + 3 * HH]);
        }

        uint4 rAh[2], rAl[2], rBh[4], rBl[4];
        auto ldg_dec = [&](int kt) {
#pragma unroll
            for (int i = 0; i < 2; i++) {           // A planes: h written by other SMs -> L2-only
                int idx = i * 256 + tid;
                int row = idx >> 4, c4 = idx & 15;
                rAh[i] = __ldcg((const uint4*)(hh + (size_t)row * HH + kt) + c4);
                rAl[i] = __ldcg((const uint4*)(hl + (size_t)row * HH + kt) + c4);
            }
#pragma unroll
            for (int i = 0; i < 4; i++) {           // B planes: constant, L1-cacheable
                int idx = i * 256 + tid;
                int row = idx >> 4, c4 = idx & 15;
                rBh[i] = *((const uint4*)(whh_hi + (size_t)row * HH + kt) + c4);
                rBl[i] = *((const uint4*)(whh_lo + (size_t)row * HH + kt) + c4);
            }
        };
        auto sts_dec = [&](int s) {
            uint32_t* Ah = sm + s * STG;
            uint32_t* Al = Ah + ASZ;
            uint32_t* Bh = Al + ASZ;
            uint32_t* Bl = Bh + BSZ;
#pragma unroll
            for (int i = 0; i < 2; i++) {
                int idx = i * 256 + tid;
                int row = idx >> 4, c4 = idx & 15;
                *(uint4*)&Ah[row * 68 + c4 * 4] = rAh[i];
                *(uint4*)&Al[row * 68 + c4 * 4] = rAl[i];
            }
#pragma unroll
            for (int i = 0; i < 4; i++) {
                int idx = i * 256 + tid;
                int row = idx >> 4, c4 = idx & 15;
                *(uint4*)&Bh[row * 68 + c4 * 4] = rBh[i];
                *(uint4*)&Bl[row * 68 + c4 * 4] = rBl[i];
            }
        };

        float acc[2][4];
#pragma unroll
        for (int mt = 0; mt < 2; mt++)
#pragma unroll
            for (int q = 0; q < 4; q++) acc[mt][q] = 0.0f;

        ldg_dec(0);
        sts_dec(0);
        __syncthreads();

        for (int ki = 0; ki < 8; ki++) {
            const int cur = ki & 1;
            if (ki + 1 < 8) ldg_dec((ki + 1) * 64);

            const uint32_t* Ah = sm + cur * STG;
            const uint32_t* Al = Ah + ASZ;
            const uint32_t* Bh = Al + ASZ;
            const uint32_t* Bl = Bh + BSZ;
#pragma unroll
            for (int ks = 0; ks < 8; ks++) {
                const int k0 = ks * 8;
                uint32_t ah[2][4], al2[2][4], bh[2], bl2[2];
#pragma unroll
                for (int mt = 0; mt < 2; mt++) {
                    int rb = mt * 16;
                    ah[mt][0] = Ah[(rb + g) * 68 + k0 + tg];
                    ah[mt][1] = Ah[(rb + g + 8) * 68 + k0 + tg];
                    ah[mt][2] = Ah[(rb + g) * 68 + k0 + tg + 4];
                    ah[mt][3] = Ah[(rb + g + 8) * 68 + k0 + tg + 4];
                    al2[mt][0] = Al[(rb + g) * 68 + k0 + tg];
                    al2[mt][1] = Al[(rb + g + 8) * 68 + k0 + tg];
                    al2[mt][2] = Al[(rb + g) * 68 + k0 + tg + 4];
                    al2[mt][3] = Al[(rb + g + 8) * 68 + k0 + tg + 4];
                }
                int nb = warp * 8 + g;
                bh[0] = Bh[nb * 68 + k0 + tg];
                bh[1] = Bh[nb * 68 + k0 + tg + 4];
                bl2[0] = Bl[nb * 68 + k0 + tg];
                bl2[1] = Bl[nb * 68 + k0 + tg + 4];
#pragma unroll
                for (int mt = 0; mt < 2; mt++) {
                    mma_tf32(acc[mt], ah[mt], bh);
                    mma_tf32(acc[mt], al2[mt], bh);
                    mma_tf32(acc[mt], ah[mt], bl2);
                }
            }

            if (ki + 1 < 8) sts_dec(1 - cur);
            __syncthreads();
        }

        // dump C [32 b, 64 n]
#pragma unroll
        for (int mt = 0; mt < 2; mt++) {
            int row = mt * 16 + g, col = warp * 8 + 2 * tg;
            dmp[row * 68 + col] = acc[mt][0];
            dmp[row * 68 + col + 1] = acc[mt][1];
            dmp[(row + 8) * 68 + col] = acc[mt][2];
            dmp[(row + 8) * 68 + col + 1] = acc[mt][3];
        }
        __syncthreads();

        // LSTM pointwise; write h fp32 + tf32 planes (parity (t+1)&1)
        uint32_t* whi = g_hpl[(t + 1) & 1][0];
        uint32_t* wlo = g_hpl[(t + 1) & 1][1];
#pragma unroll
        for (int rep = 0; rep < 2; rep++) {
            int u = tid + rep * 256;
            int b = u >> 4, jj = u & 15;
            float iv = dmp[b * 68 + jj]      + gx[rep][0];
            float fv = dmp[b * 68 + 16 + jj] + gx[rep][1];
            float gv = dmp[b * 68 + 32 + jj] + gx[rep][2];
            float ov = dmp[b * 68 + 48 + jj] + gx[rep][3];
            float cn = sigf(fv) * csh[u] + sigf(iv) * tanhf(gv);
            float hn = sigf(ov) * tanhf(cn);
            csh[u] = cn;
            __stcg(&g_hhist[((size_t)b * TT + t) * HH + jb + jj], hn);
            uint32_t hi = f2tf32(hn);
            __stcg(&whi[b * HH + jb + jj], hi);
            __stcg(&wlo[b * HH + jb + jj], f2tf32(hn - __uint_as_float(hi)));
        }
        __threadfence();
        __syncthreads();
        if (tid == 0) {
            atomicAdd(&g_bar[t], 1u);
            while (atomicAdd(&g_bar[t], 0u) < NDEC) {}
        }
        __syncthreads();
    }
}

// ---------------- post-loop: scores + softmax (parallel over b) ----------
__global__ __launch_bounds__(256) void k_scores(const int* __restrict__ lens)
{
    extern __shared__ uint32_t dynsm[];
    uint32_t* Ah = dynsm;                 // 64*20
    uint32_t* Al = Ah + 64 * 20;
    uint32_t* Bh = Al + 64 * 20;          // 128*20
    uint32_t* Bl = Bh + 128 * 20;
    float* sc = (float*)dynsm;            // 64*132 overlay (phase-separated)

    const int b = blockIdx.x, tid = threadIdx.x;
    const int warp = tid >> 5, lane = tid & 31, g = lane >> 2, tg = lane & 3;
    const int wm = (warp & 1) * 32, wn = (warp >> 1) * 32;

    float acc[2][4][4];
#pragma unroll
    for (int i = 0; i < 2; i++)
#pragma unroll
        for (int j = 0; j < 4; j++)
#pragma unroll
            for (int q = 0; q < 4; q++) acc[i][j][q] = 0.0f;

    for (int kt = 0; kt < HH; kt += 16) {
        {
            int row = tid >> 2, c4 = tid & 3;
            float4 v = *((const float4*)(g_hhist + ((size_t)b * TT + row) * HH + kt) + c4);
            float av[4] = {v.x, v.y, v.z, v.w};
            uint32_t* da = &Ah[row * 20 + c4 * 4];
            uint32_t* dl = &Al[row * 20 + c4 * 4];
#pragma unroll
            for (int q = 0; q < 4; q++) {
                uint32_t h = f2tf32(av[q]);
                da[q] = h;
                dl[q] = f2tf32(av[q] - __uint_as_float(h));
            }
        }
#pragma unroll
        for (int i = 0; i < 2; i++) {
            int idx = i * 256 + tid;
            int row = idx >> 2, c4 = idx & 3;
            float4 v = *((const float4*)(g_proj_enc + ((size_t)b * SS + row) * HH + kt) + c4);
            float bv[4] = {v.x, v.y, v.z, v.w};
            uint32_t* db = &Bh[row * 20 + c4 * 4];
            uint32_t* dl = &Bl[row * 20 + c4 * 4];
#pragma unroll
            for (int q = 0; q < 4; q++) {
                uint32_t h = f2tf32(bv[q]);
                db[q] = h;
                dl[q] = f2tf32(bv[q] - __uint_as_float(h));
            }
        }
        __syncthreads();
#pragma unroll
        for (int ks = 0; ks < 2; ks++) {
            const int k0 = ks * 8;
            uint32_t ah[2][4], al2[2][4], bh[4][2], bl2[4][2];
#pragma unroll
            for (int mt = 0; mt < 2; mt++) {
                int rb = wm + mt * 16;
                ah[mt][0] = Ah[(rb + g) * 20 + k0 + tg];
                ah[mt][1] = Ah[(rb + g + 8) * 20 + k0 + tg];
                ah[mt][2] = Ah[(rb + g) * 20 + k0 + tg + 4];
                ah[mt][3] = Ah[(rb + g + 8) * 20 + k0 + tg + 4];
                al2[mt][0] = Al[(rb + g) * 20 + k0 + tg];
                al2[mt][1] = Al[(rb + g + 8) * 20 + k0 + tg];
                al2[mt][2] = Al[(rb + g) * 20 + k0 + tg + 4];
                al2[mt][3] = Al[(rb + g + 8) * 20 + k0 + tg + 4];
            }
#pragma unroll
            for (int nt = 0; nt < 4; nt++) {
                int nb = wn + nt * 8 + g;
                bh[nt][0] = Bh[nb * 20 + k0 + tg];
                bh[nt][1] = Bh[nb * 20 + k0 + tg + 4];
                bl2[nt][0] = Bl[nb * 20 + k0 + tg];
                bl2[nt][1] = Bl[nb * 20 + k0 + tg + 4];
            }
#pragma unroll
            for (int mt = 0; mt < 2; mt++)
#pragma unroll
                for (int nt = 0; nt < 4; nt++) {
                    mma_tf32(acc[mt][nt], ah[mt], bh[nt]);
                    mma_tf32(acc[mt][nt], al2[mt], bh[nt]);
                    mma_tf32(acc[mt][nt], ah[mt], bl2[nt]);
                }
        }
        __syncthreads();
    }

#pragma unroll
    for (int mt = 0; mt < 2; mt++)
#pragma unroll
        for (int nt = 0; nt < 4; nt++) {
            int row = wm + mt * 16 + g, col = wn + nt * 8 + 2 * tg;
            sc[row * 132 + col] = acc[mt][nt][0];
            sc[row * 132 + col + 1] = acc[mt][nt][1];
            sc[(row + 8) * 132 + col] = acc[mt][nt][2];
            sc[(row + 8) * 132 + col + 1] = acc[mt][nt][3];
        }
    __syncthreads();

    const int len = lens[b];
    for (int i = 0; i < 8; i++) {
        int t = warp * 8 + i;
        float v[4], mx = -3.0e38f;
#pragma unroll
        for (int q = 0; q < 4; q++) {
            int s = lane + q * 32;
            v[q] = (s < len) ? sc[t * 132 + s] : -3.0e38f;
            mx = fmaxf(mx, v[q]);
        }
        for (int off = 16; off > 0; off >>= 1)
            mx = fmaxf(mx, __shfl_xor_sync(0xFFFFFFFFu, mx, off));
        float e[4], sum = 0.0f;
#pragma unroll
        for (int q = 0; q < 4; q++) {
            int s = lane + q * 32;
            e[q] = (s < len) ? expf(v[q] - mx) : 0.0f;
            sum += e[q];
        }
        for (int off = 16; off > 0; off >>= 1)
            sum += __shfl_xor_sync(0xFFFFFFFFu, sum, off);
        float inv = 1.0f / sum;
#pragma unroll
        for (int q = 0; q < 4; q++)
            g_att2[((size_t)b * TT + t) * SS + lane + q * 32] = e[q] * inv;
    }
}

// ---------------- post-loop: HO += att @ proj2 (batched per b) ----------
__global__ __launch_bounds__(256) void k_ctx()
{
    __shared__ float att_sh[TT * SS];
    const int b = blockIdx.y, jt = blockIdx.x, tid = threadIdx.x;

    for (int i = tid; i < TT * SS / 4; i += 256)
        ((float4*)att_sh)[i] = ((const float4*)(g_att2 + (size_t)b * TT * SS))[i];
    __syncthreads();

    const int j = jt * 128 + (tid & 127);
    const int th = tid >> 7;
    float acc[32];
#pragma unroll
    for (int tt = 0; tt < 32; tt++) acc[tt] = 0.0f;

    const float* p2 = g_proj2 + (size_t)b * SS * HH + j;
    const float* ar = att_sh + (th * 32) * SS;
#pragma unroll 4
    for (int s = 0; s < SS; s++) {
        float v = p2[(size_t)s * HH];
#pragma unroll
        for (int tt = 0; tt < 32; tt++)
            acc[tt] += ar[tt * SS + s] * v;
    }
#pragma unroll
    for (int tt = 0; tt < 32; tt++) {
        size_t o = ((size_t)b * TT + th * 32 + tt) * HH + j;
        g_ho[o] += acc[tt];
    }
}

// ---------------- launcher ----------------
extern "C" void kernel_launch(void* const* d_in, const int* in_sizes, int n_in,
                              void* d_out, int out_size)
{
    const int* tok = (const int*)d_in[0];
    const float* enc = (const float*)d_in[1];
    const int* lens = (const int*)d_in[2];
    const float* h0 = (const float*)d_in[3];
    const float* c0 = (const float*)d_in[4];
    const float* emb = (const float*)d_in[5];
    const float* Wih = (const float*)d_in[6];
    const float* Whh = (const float*)d_in[7];
    const float* bih = (const float*)d_in[8];
    const float* bhh = (const float*)d_in[9];
    const float* Wa = (const float*)d_in[10];
    const float* Wcw = (const float*)d_in[11];
    const float* Wcb = (const float*)d_in[12];
    const float* Wow = (const float*)d_in[13];
    const float* Wob = (const float*)d_in[14];
    float* out = (float*)d_out;

    float *p_gatesx, *p_hhist, *p_proj, *p_proj2, *p_ho, *p_bias;
    cudaGetSymbolAddress((void**)&p_gatesx, g_gatesx);
    cudaGetSymbolAddress((void**)&p_hhist, g_hhist);
    cudaGetSymbolAddress((void**)&p_proj, g_proj_enc);
    cudaGetSymbolAddress((void**)&p_proj2, g_proj2);
    cudaGetSymbolAddress((void**)&p_ho, g_ho);
    cudaGetSymbolAddress((void**)&p_bias, g_bias2);

    // smem opt-ins (one per template instantiation!)
    const int NC_DYN = 2 * 2 * (128 * 36) * 4;          // 73,728 B
    const int CP_DYN = 2 * 2 * (2 * 128 * 20) * 4;      // 81,920 B
    cudaFuncSetAttribute(gemm_db<false, true>,  cudaFuncAttributeMaxDynamicSharedMemorySize, NC_DYN);
    cudaFuncSetAttribute(gemm_db<false, false>, cudaFuncAttributeMaxDynamicSharedMemorySize, NC_DYN);
    cudaFuncSetAttribute(gemm_db<true, false>,  cudaFuncAttributeMaxDynamicSharedMemorySize, CP_DYN);

    const int DEC_DYN = (2 * (2 * 32 * 68 + 2 * 64 * 68) + 32 * 68 + 512) * 4;  // 115,200 B
    cudaFuncSetAttribute(k_decode, cudaFuncAttributeMaxDynamicSharedMemorySize, DEC_DYN);
    const int SC_DYN = 64 * 132 * 4;                    // 33,792 B
    cudaFuncSetAttribute(k_scores, cudaFuncAttributeMaxDynamicSharedMemorySize, SC_DYN);

    // init + prep (all kernels; capture-safe)
    k_zero_bar<<<1, 64>>>();
    k_bias<<<8, 256>>>(bih, bhh);
    k_prep_whh<<<(2048 * 128 + 255) / 256, 256>>>(Whh);
    k_prep_h0<<<(BB * HH / 4 + 255) / 256, 256>>>(h0);

    // A1: gates_x[B*T, 4H] = emb[tok] @ W_ih^T + (b_ih + b_hh)
    gemm_db<false, true><<<dim3(4 * HH / 128, BB * TT / 128), 256, NC_DYN>>>(
        emb, EE, tok, Wih, EE, p_gatesx, 4 * HH, p_bias, EE);

    // A2: proj_enc = enc @ Wa^T   (compensated tf32)
    gemm_db<true, false><<<dim3(HH / 128, BB * SS / 128), 256, CP_DYN>>>(
        enc, ENCC, nullptr, Wa, ENCC, p_proj, HH, nullptr, ENCC);

    // A3: proj2 = enc @ Wc_c^T    (Wc_c = Wc_w[:, H:], row stride H+ENC)
    gemm_db<true, false><<<dim3(HH / 128, BB * SS / 128), 256, CP_DYN>>>(
        enc, ENCC, nullptr, Wcw + HH, HH + ENCC, p_proj2, HH, nullptr, ENCC);

    // sequential LSTM recurrence: ONE persistent kernel, 64 steps internally
    k_decode<<<NDEC, 256, DEC_DYN>>>(c0);

    // off-critical-path work, all parallel:
    k_scores<<<BB, 256, SC_DYN>>>(lens);

    // HO = Hhist @ Wc_h^T + Wcb   (compensated tf32; Wc_h = Wc_w[:, :H])
    gemm_db<true, false><<<dim3(HH / 128, BB * TT / 128), 256, CP_DYN>>>(
        p_hhist, HH, nullptr, Wcw, HH + ENCC, p_ho, HH, Wcb, HH);

    k_ctx<<<dim3(4, BB), 256>>>();

    // D: logits = HO @ Wo^T + Wo_b
    gemm_db<false, false><<<dim3(VV / 128, BB * TT / 128), 256, NC_DYN>>>(
        p_ho, HH, nullptr, Wow, HH, out, VV, Wob, HH);
}